// round 4
// baseline (speedup 1.0000x reference)
#include <cuda_runtime.h>
#include <math.h>

// Problem constants  (L,G,H,R,S,A,B = 4,8,2048,128,512,64,4096)
#define BB 4096   // batch
#define SS 512    // input dim
#define HH 2048   // hidden
#define RR 128    // low-rank dim
#define AA 64     // output dim
#define GG 8      // experts
#define LL 4      // layers

// Scratch (device globals — no allocations allowed)
__device__ __align__(16) float g_x[(size_t)BB * HH];    // activations
__device__ __align__(16) float g_y[(size_t)BB * HH];    // main-branch accum
__device__ __align__(16) float g_h1[(size_t)BB * RR];   // low-rank intermediate
__device__ int g_cnt[GG];
__device__ int g_rows[GG * BB];
__device__ const float* g_bg1_ptr;   // resolved on device (o vs b_g1 ambiguity)

// ---------------------------------------------------------------------------
// Routing. The two size-4096 inputs {o, b_g1} are ambiguous to the host.
// Identify `o` by content: int32 values in [0,GG) with at least one nonzero
// (b_g1 is all-zero; also handles int64 `o` as [v,0] word pairs). The other
// candidate is published as b_g1 via g_bg1_ptr. Single block.
// ---------------------------------------------------------------------------
__global__ void build_routing(const int* __restrict__ c0,
                              const int* __restrict__ c1)
{
    __shared__ const int* o_ptr;
    __shared__ int stride;
    int tid = threadIdx.x;
    if (tid == 0) {
        const int* cands[2] = {c0, c1};
        int pick = 0; stride = 1;
        for (int c = 0; c < 2; c++) {
            const int* p = cands[c];
            bool ok32 = true, nz32 = false;
            for (int i = 0; i < 256; i++) {
                int v = p[i];
                if (v < 0 || v >= GG) { ok32 = false; break; }
                if (v) nz32 = true;
            }
            if (ok32 && nz32) { pick = c; stride = 1; break; }
            bool ok64 = true, nz64 = false;
            for (int i = 0; i < 256; i++) {
                int lo = p[2 * i], hi = p[2 * i + 1];
                if (hi != 0 || lo < 0 || lo >= GG) { ok64 = false; break; }
                if (lo) nz64 = true;
            }
            if (ok64 && nz64) { pick = c; stride = 2; break; }
        }
        o_ptr = cands[pick];
        g_bg1_ptr = (const float*)cands[1 - pick];
    }
    if (tid < GG) g_cnt[tid] = 0;
    __syncthreads();
    const int* o = o_ptr;
    const int st = stride;
    for (int b = tid; b < BB; b += blockDim.x) {
        int e = o[(size_t)b * st];
        int idx = atomicAdd(&g_cnt[e], 1);
        g_rows[e * BB + idx] = b;
    }
}

// ---------------------------------------------------------------------------
// Dense SGEMM: C[M,N] = A[M,K] @ Bm[K,N] + bias[N]
// BM=BN=128, BK=8, 256 threads, 8x8 per thread. M,N mult of 128; K mult of 8.
// ---------------------------------------------------------------------------
__global__ __launch_bounds__(256, 2)
void sgemm_bias(const float* __restrict__ A, const float* __restrict__ Bm,
                const float* __restrict__ bias, float* __restrict__ C,
                int M, int N, int K)
{
    __shared__ __align__(16) float As[8][128];
    __shared__ __align__(16) float Bs[8][128];
    const int tid = threadIdx.x;
    const int tx = tid & 15, ty = tid >> 4;
    const int row0 = blockIdx.y * 128;
    const int col0 = blockIdx.x * 128;

    const int a_row = tid >> 1;
    const int a_col = (tid & 1) * 4;
    const int b_row = tid >> 5;
    const int b_col = (tid & 31) * 4;

    float acc[8][8];
#pragma unroll
    for (int i = 0; i < 8; i++)
#pragma unroll
        for (int j = 0; j < 8; j++) acc[i][j] = 0.0f;

    for (int k0 = 0; k0 < K; k0 += 8) {
        float4 av = *(const float4*)(A + (size_t)(row0 + a_row) * K + k0 + a_col);
        As[a_col + 0][a_row] = av.x;
        As[a_col + 1][a_row] = av.y;
        As[a_col + 2][a_row] = av.z;
        As[a_col + 3][a_row] = av.w;
        *(float4*)(&Bs[b_row][b_col]) =
            *(const float4*)(Bm + (size_t)(k0 + b_row) * N + col0 + b_col);
        __syncthreads();
#pragma unroll
        for (int k = 0; k < 8; k++) {
            float4 a0 = *(const float4*)(&As[k][ty * 8]);
            float4 a1 = *(const float4*)(&As[k][ty * 8 + 4]);
            float4 b0 = *(const float4*)(&Bs[k][tx * 8]);
            float4 b1 = *(const float4*)(&Bs[k][tx * 8 + 4]);
            float ar[8] = {a0.x, a0.y, a0.z, a0.w, a1.x, a1.y, a1.z, a1.w};
            float br[8] = {b0.x, b0.y, b0.z, b0.w, b1.x, b1.y, b1.z, b1.w};
#pragma unroll
            for (int i = 0; i < 8; i++)
#pragma unroll
                for (int j = 0; j < 8; j++) acc[i][j] = fmaf(ar[i], br[j], acc[i][j]);
        }
        __syncthreads();
    }

#pragma unroll
    for (int i = 0; i < 8; i++) {
        int r = row0 + ty * 8 + i;
#pragma unroll
        for (int j = 0; j < 8; j += 4) {
            int c = col0 + tx * 8 + j;
            float4 v;
            v.x = acc[i][j + 0] + bias[c + 0];
            v.y = acc[i][j + 1] + bias[c + 1];
            v.z = acc[i][j + 2] + bias[c + 2];
            v.w = acc[i][j + 3] + bias[c + 3];
            *(float4*)(C + (size_t)r * N + c) = v;
        }
    }
}

// ---------------------------------------------------------------------------
// Output GEMM: out[M, 64] = A[M, K] @ W[K, 64] + bias[64]
// BM=128, BN=64, BK=8, 256 threads, 8x4 per thread.
// ---------------------------------------------------------------------------
__global__ __launch_bounds__(256, 2)
void sgemm_out(const float* __restrict__ A, const float* __restrict__ W,
               const float* __restrict__ bias, float* __restrict__ C, int K)
{
    __shared__ __align__(16) float As[8][128];
    __shared__ __align__(16) float Bs[8][64];
    const int tid = threadIdx.x;
    const int tx = tid & 15, ty = tid >> 4;
    const int row0 = blockIdx.y * 128;

    const int a_row = tid >> 1;
    const int a_col = (tid & 1) * 4;

    float acc[8][4];
#pragma unroll
    for (int i = 0; i < 8; i++)
#pragma unroll
        for (int j = 0; j < 4; j++) acc[i][j] = 0.0f;

    for (int k0 = 0; k0 < K; k0 += 8) {
        float4 av = *(const float4*)(A + (size_t)(row0 + a_row) * K + k0 + a_col);
        As[a_col + 0][a_row] = av.x;
        As[a_col + 1][a_row] = av.y;
        As[a_col + 2][a_row] = av.z;
        As[a_col + 3][a_row] = av.w;
        if (tid < 128) {
            int br = tid >> 4, bc = (tid & 15) * 4;
            *(float4*)(&Bs[br][bc]) =
                *(const float4*)(W + (size_t)(k0 + br) * AA + bc);
        }
        __syncthreads();
#pragma unroll
        for (int k = 0; k < 8; k++) {
            float4 a0 = *(const float4*)(&As[k][ty * 8]);
            float4 a1 = *(const float4*)(&As[k][ty * 8 + 4]);
            float4 b0 = *(const float4*)(&Bs[k][tx * 4]);
            float ar[8] = {a0.x, a0.y, a0.z, a0.w, a1.x, a1.y, a1.z, a1.w};
            float br[4] = {b0.x, b0.y, b0.z, b0.w};
#pragma unroll
            for (int i = 0; i < 8; i++)
#pragma unroll
                for (int j = 0; j < 4; j++) acc[i][j] = fmaf(ar[i], br[j], acc[i][j]);
        }
        __syncthreads();
    }

    const int c = tx * 4;
    float4 bv = *(const float4*)(bias + c);
#pragma unroll
    for (int i = 0; i < 8; i++) {
        int r = row0 + ty * 8 + i;
        float4 v;
        v.x = acc[i][0] + bv.x;
        v.y = acc[i][1] + bv.y;
        v.z = acc[i][2] + bv.z;
        v.w = acc[i][3] + bv.w;
        *(float4*)(C + (size_t)r * AA + c) = v;
    }
}

// ---------------------------------------------------------------------------
// Grouped g1: expert g = blockIdx.z, rows gathered via g_rows.
// h1[row, :] = x[row, :] @ W_g1[l,g] + b_g1[l,g].  N = RR = 128.
// Bias pointer comes from g_bg1_ptr (resolved by build_routing).
// ---------------------------------------------------------------------------
__global__ __launch_bounds__(256, 2)
void sgemm_g1_grouped(const float* __restrict__ Wg1, int l)
{
    const int g = blockIdx.z;
    const int cnt = g_cnt[g];
    const int mbase = blockIdx.y * 128;
    if (mbase >= cnt) return;
    const int* rows = g_rows + g * BB;

    const float* Bm   = Wg1 + ((size_t)(l * GG + g)) * HH * RR;
    const float* bias = g_bg1_ptr + (size_t)(l * GG + g) * 0;  // b_g1 is [L,G,R]
    bias = g_bg1_ptr;  // base
    const float* bias_lg = bias + ((size_t)0);
    // NOTE: b_g1 has shape [L*G*R] but L*G*R = 4096 total and our slice is
    // (l*GG+g)*RR .. +RR. Keep the proper offset:
    const float* bslice = g_bg1_ptr + (size_t)(l * GG + g) * RR % 4096;
    (void)bias_lg;

    __shared__ __align__(16) float As[8][128];
    __shared__ __align__(16) float Bs[8][128];
    const int tid = threadIdx.x;
    const int tx = tid & 15, ty = tid >> 4;

    const int a_row = tid >> 1;
    const int a_col = (tid & 1) * 4;
    const int b_row = tid >> 5;
    const int b_col = (tid & 31) * 4;

    int lr = mbase + a_row;
    int src_row = rows[lr < cnt ? lr : (cnt - 1)];  // clamp; epilogue guards writes

    float acc[8][8];
#pragma unroll
    for (int i = 0; i < 8; i++)
#pragma unroll
        for (int j = 0; j < 8; j++) acc[i][j] = 0.0f;

    for (int k0 = 0; k0 < HH; k0 += 8) {
        float4 av = *(const float4*)(g_x + (size_t)src_row * HH + k0 + a_col);
        As[a_col + 0][a_row] = av.x;
        As[a_col + 1][a_row] = av.y;
        As[a_col + 2][a_row] = av.z;
        As[a_col + 3][a_row] = av.w;
        *(float4*)(&Bs[b_row][b_col]) =
            *(const float4*)(Bm + (size_t)(k0 + b_row) * RR + b_col);
        __syncthreads();
#pragma unroll
        for (int k = 0; k < 8; k++) {
            float4 a0 = *(const float4*)(&As[k][ty * 8]);
            float4 a1 = *(const float4*)(&As[k][ty * 8 + 4]);
            float4 b0 = *(const float4*)(&Bs[k][tx * 8]);
            float4 b1 = *(const float4*)(&Bs[k][tx * 8 + 4]);
            float ar[8] = {a0.x, a0.y, a0.z, a0.w, a1.x, a1.y, a1.z, a1.w};
            float br[8] = {b0.x, b0.y, b0.z, b0.w, b1.x, b1.y, b1.z, b1.w};
#pragma unroll
            for (int i = 0; i < 8; i++)
#pragma unroll
                for (int j = 0; j < 8; j++) acc[i][j] = fmaf(ar[i], br[j], acc[i][j]);
        }
        __syncthreads();
    }

#pragma unroll
    for (int i = 0; i < 8; i++) {
        int lrw = mbase + ty * 8 + i;
        if (lrw >= cnt) continue;
        int row = rows[lrw];
#pragma unroll
        for (int j = 0; j < 8; j += 4) {
            int c = tx * 8 + j;
            float4 v;
            v.x = acc[i][j + 0] + bslice[c + 0];
            v.y = acc[i][j + 1] + bslice[c + 1];
            v.z = acc[i][j + 2] + bslice[c + 2];
            v.w = acc[i][j + 3] + bslice[c + 3];
            *(float4*)(g_h1 + (size_t)row * RR + c) = v;
        }
    }
}

// ---------------------------------------------------------------------------
// Grouped g2 + fuse: x_next[row,c] = elu( y[row,c] + h1[row,:]@W_g2[l,g][:,c]
//                                         + b_g2[l,g,c] )
// ---------------------------------------------------------------------------
__global__ __launch_bounds__(256, 2)
void sgemm_g2_fused(const float* __restrict__ Wg2, const float* __restrict__ bg2,
                    int l)
{
    const int g = blockIdx.z;
    const int cnt = g_cnt[g];
    const int mbase = blockIdx.y * 128;
    if (mbase >= cnt) return;
    const int* rows = g_rows + g * BB;
    const int col0 = blockIdx.x * 128;

    const float* Bm   = Wg2 + ((size_t)(l * GG + g)) * RR * HH;
    const float* bias = bg2 + (size_t)(l * GG + g) * HH;

    __shared__ __align__(16) float As[8][128];
    __shared__ __align__(16) float Bs[8][128];
    const int tid = threadIdx.x;
    const int tx = tid & 15, ty = tid >> 4;

    const int a_row = tid >> 1;
    const int a_col = (tid & 1) * 4;
    const int b_row = tid >> 5;
    const int b_col = (tid & 31) * 4;

    int lr = mbase + a_row;
    int src_row = rows[lr < cnt ? lr : (cnt - 1)];

    float acc[8][8];
#pragma unroll
    for (int i = 0; i < 8; i++)
#pragma unroll
        for (int j = 0; j < 8; j++) acc[i][j] = 0.0f;

    for (int k0 = 0; k0 < RR; k0 += 8) {
        float4 av = *(const float4*)(g_h1 + (size_t)src_row * RR + k0 + a_col);
        As[a_col + 0][a_row] = av.x;
        As[a_col + 1][a_row] = av.y;
        As[a_col + 2][a_row] = av.z;
        As[a_col + 3][a_row] = av.w;
        *(float4*)(&Bs[b_row][b_col]) =
            *(const float4*)(Bm + (size_t)(k0 + b_row) * HH + col0 + b_col);
        __syncthreads();
#pragma unroll
        for (int k = 0; k < 8; k++) {
            float4 a0 = *(const float4*)(&As[k][ty * 8]);
            float4 a1 = *(const float4*)(&As[k][ty * 8 + 4]);
            float4 b0 = *(const float4*)(&Bs[k][tx * 8]);
            float4 b1 = *(const float4*)(&Bs[k][tx * 8 + 4]);
            float ar[8] = {a0.x, a0.y, a0.z, a0.w, a1.x, a1.y, a1.z, a1.w};
            float br[8] = {b0.x, b0.y, b0.z, b0.w, b1.x, b1.y, b1.z, b1.w};
#pragma unroll
            for (int i = 0; i < 8; i++)
#pragma unroll
                for (int j = 0; j < 8; j++) acc[i][j] = fmaf(ar[i], br[j], acc[i][j]);
        }
        __syncthreads();
    }

#pragma unroll
    for (int i = 0; i < 8; i++) {
        int lrw = mbase + ty * 8 + i;
        if (lrw >= cnt) continue;
        int row = rows[lrw];
#pragma unroll
        for (int j = 0; j < 8; j += 4) {
            int c = col0 + tx * 8 + j;
            float4 ym = *(const float4*)(g_y + (size_t)row * HH + c);
            float4 v;
            v.x = ym.x + acc[i][j + 0] + bias[c + 0];
            v.y = ym.y + acc[i][j + 1] + bias[c + 1];
            v.z = ym.z + acc[i][j + 2] + bias[c + 2];
            v.w = ym.w + acc[i][j + 3] + bias[c + 3];
            // ELU (alpha = 1): x > 0 ? x : expm1(x)
            v.x = v.x > 0.0f ? v.x : expm1f(v.x);
            v.y = v.y > 0.0f ? v.y : expm1f(v.y);
            v.z = v.z > 0.0f ? v.z : expm1f(v.z);
            v.w = v.w > 0.0f ? v.w : expm1f(v.w);
            *(float4*)(g_x + (size_t)row * HH + c) = v;
        }
    }
}

// ---------------------------------------------------------------------------
// Launch — inputs classified by SIZE (permutation-independent):
//   2097152 -> s        1048576 -> W_in    2048 -> b_in
//   16777216 -> W_main  8192 -> b_main     65536 -> b_g2
//   131072 -> W_out     64 -> b_out
//   8388608 (x2, encounter order) -> W_g1, W_g2
//   4096 (x2) -> {o, b_g1}: resolved on-device by content.
// ---------------------------------------------------------------------------
extern "C" void kernel_launch(void* const* d_in, const int* in_sizes, int n_in,
                              void* d_out, int out_size)
{
    const float* s = 0; const float* W_in = 0; const float* b_in = 0;
    const float* W_main = 0; const float* b_main = 0; const float* b_g2 = 0;
    const float* W_out = 0; const float* b_out = 0;
    const float* w8[2] = {0, 0};
    const void*  c4[2] = {0, 0};
    int n8 = 0, n4 = 0;

    for (int i = 0; i < n_in; i++) {
        switch (in_sizes[i]) {
            case 2097152:  s      = (const float*)d_in[i]; break;
            case 1048576:  W_in   = (const float*)d_in[i]; break;
            case 2048:     b_in   = (const float*)d_in[i]; break;
            case 16777216: W_main = (const float*)d_in[i]; break;
            case 8192:     b_main = (const float*)d_in[i]; break;
            case 65536:    b_g2   = (const float*)d_in[i]; break;
            case 131072:   W_out  = (const float*)d_in[i]; break;
            case 64:       b_out  = (const float*)d_in[i]; break;
            case 8388608:  if (n8 < 2) w8[n8++] = (const float*)d_in[i]; break;
            case 4096:     if (n4 < 2) c4[n4++] = d_in[i]; break;
            default: break;
        }
    }
    const float* W_g1 = w8[0];
    const float* W_g2 = w8[1];
    float* out = (float*)d_out;

    float* x_ptr;  cudaGetSymbolAddress((void**)&x_ptr, g_x);
    float* y_ptr;  cudaGetSymbolAddress((void**)&y_ptr, g_y);

    dim3 blk(256);

    // routing (identifies `o` vs b_g1 among the size-4096 pair, on device)
    build_routing<<<1, 256>>>((const int*)c4[0], (const int*)c4[1]);

    // x = s @ W_in + b_in   [4096,512]x[512,2048]
    sgemm_bias<<<dim3(HH / 128, BB / 128), blk>>>(s, W_in, b_in, x_ptr, BB, HH, SS);

    for (int l = 0; l < LL; l++) {
        // y = x @ W_main[l] + b_main[l]
        sgemm_bias<<<dim3(HH / 128, BB / 128), blk>>>(
            x_ptr, W_main + (size_t)l * HH * HH, b_main + (size_t)l * HH,
            y_ptr, BB, HH, HH);
        // h1 = gather(x) @ W_g1[l, o] + b_g1
        sgemm_g1_grouped<<<dim3(1, BB / 128, GG), blk>>>(W_g1, l);
        // x = elu(y + h1 @ W_g2[l, o] + b_g2)
        sgemm_g2_fused<<<dim3(HH / 128, BB / 128, GG), blk>>>(W_g2, b_g2, l);
    }

    // out = x @ W_out + b_out   [4096,2048]x[2048,64]
    sgemm_out<<<dim3(1, BB / 128), blk>>>(x_ptr, W_out, b_out, out, HH);
}

// round 5
// speedup vs baseline: 2.4547x; 2.4547x over previous
#include <cuda_runtime.h>
#include <math.h>
#include <stdint.h>

// Problem constants  (L,G,H,R,S,A,B = 4,8,2048,128,512,64,4096)
#define BB 4096
#define SS 512
#define HH 2048
#define RR 128
#define AA 64
#define GG 8
#define LL 4

// Scratch
__device__ __align__(16) float g_x[(size_t)BB * HH];
__device__ __align__(16) float g_y[(size_t)BB * HH];
__device__ __align__(16) float g_h1[(size_t)BB * RR];
__device__ int g_cnt[GG];
__device__ int g_rows[GG * BB];
__device__ const float* g_bg1_ptr;

// ---------------------------------------------------------------------------
// helpers
// ---------------------------------------------------------------------------
__device__ __forceinline__ uint32_t f2tf32(float v) {
    uint32_t u;
    asm("cvt.rna.tf32.f32 %0, %1;" : "=r"(u) : "f"(v));
    return u;
}
__device__ __forceinline__ void mma_tf32(float* d, const uint32_t* a,
                                         const uint32_t* b) {
    asm volatile(
        "mma.sync.aligned.m16n8k8.row.col.f32.tf32.tf32.f32 "
        "{%0,%1,%2,%3}, {%4,%5,%6,%7}, {%8,%9}, {%0,%1,%2,%3};"
        : "+f"(d[0]), "+f"(d[1]), "+f"(d[2]), "+f"(d[3])
        : "r"(a[0]), "r"(a[1]), "r"(a[2]), "r"(a[3]), "r"(b[0]), "r"(b[1]));
}
__device__ __forceinline__ float elu1(float v) {
    return v > 0.0f ? v : expm1f(v);
}

// ---------------------------------------------------------------------------
// Routing (also resolves the {o, b_g1} size-4096 ambiguity by content)
// ---------------------------------------------------------------------------
__global__ void build_routing(const int* __restrict__ c0,
                              const int* __restrict__ c1)
{
    __shared__ const int* o_ptr;
    __shared__ int stride;
    int tid = threadIdx.x;
    if (tid == 0) {
        const int* cands[2] = {c0, c1};
        int pick = 0; stride = 1;
        for (int c = 0; c < 2; c++) {
            const int* p = cands[c];
            bool ok32 = true, nz32 = false;
            for (int i = 0; i < 256; i++) {
                int v = p[i];
                if (v < 0 || v >= GG) { ok32 = false; break; }
                if (v) nz32 = true;
            }
            if (ok32 && nz32) { pick = c; stride = 1; break; }
            bool ok64 = true, nz64 = false;
            for (int i = 0; i < 256; i++) {
                int lo = p[2 * i], hi = p[2 * i + 1];
                if (hi != 0 || lo < 0 || lo >= GG) { ok64 = false; break; }
                if (lo) nz64 = true;
            }
            if (ok64 && nz64) { pick = c; stride = 2; break; }
        }
        o_ptr = cands[pick];
        g_bg1_ptr = (const float*)cands[1 - pick];
    }
    if (tid < GG) g_cnt[tid] = 0;
    __syncthreads();
    const int* o = o_ptr;
    const int st = stride;
    for (int b = tid; b < BB; b += blockDim.x) {
        int e = o[(size_t)b * st];
        int idx = atomicAdd(&g_cnt[e], 1);
        g_rows[e * BB + idx] = b;
    }
}

// ---------------------------------------------------------------------------
// Dense tf32 tensor-core GEMM: C[M,N] = A[M,K] @ B[K,N] + bias
// BM=BN=128, BK=16, 256 threads (8 warps, each 64x32).
// M,N mult of 128; K mult of 16.
// ---------------------------------------------------------------------------
#define PADD 136
__global__ __launch_bounds__(256)
void tgemm_bias(const float* __restrict__ A, const float* __restrict__ Bm,
                const float* __restrict__ bias, float* __restrict__ C,
                int M, int N, int K)
{
    __shared__ uint32_t As[16][PADD];
    __shared__ uint32_t Bs[16][PADD];
    const int tid = threadIdx.x;
    const int lane = tid & 31, wid = tid >> 5;
    const int wm = (wid & 1) * 64;
    const int wn = (wid >> 1) * 32;
    const int row0 = blockIdx.y * 128, col0 = blockIdx.x * 128;
    const int r = lane >> 2, cq = lane & 3;

    const int a_row = tid >> 1, a_col = (tid & 1) * 8;
    const int b_row = tid >> 4, b_col = (tid & 15) * 8;

    float acc[4][4][4];
#pragma unroll
    for (int t = 0; t < 4; t++)
#pragma unroll
        for (int u = 0; u < 4; u++)
#pragma unroll
            for (int v = 0; v < 4; v++) acc[t][u][v] = 0.0f;

    for (int k0 = 0; k0 < K; k0 += 16) {
        const float* ap = A + (size_t)(row0 + a_row) * K + k0 + a_col;
        float4 av0 = *(const float4*)ap;
        float4 av1 = *(const float4*)(ap + 4);
        As[a_col + 0][a_row] = f2tf32(av0.x);
        As[a_col + 1][a_row] = f2tf32(av0.y);
        As[a_col + 2][a_row] = f2tf32(av0.z);
        As[a_col + 3][a_row] = f2tf32(av0.w);
        As[a_col + 4][a_row] = f2tf32(av1.x);
        As[a_col + 5][a_row] = f2tf32(av1.y);
        As[a_col + 6][a_row] = f2tf32(av1.z);
        As[a_col + 7][a_row] = f2tf32(av1.w);

        const float* bp = Bm + (size_t)(k0 + b_row) * N + col0 + b_col;
        float4 bv0 = *(const float4*)bp;
        float4 bv1 = *(const float4*)(bp + 4);
        Bs[b_row][b_col + 0] = f2tf32(bv0.x);
        Bs[b_row][b_col + 1] = f2tf32(bv0.y);
        Bs[b_row][b_col + 2] = f2tf32(bv0.z);
        Bs[b_row][b_col + 3] = f2tf32(bv0.w);
        Bs[b_row][b_col + 4] = f2tf32(bv1.x);
        Bs[b_row][b_col + 5] = f2tf32(bv1.y);
        Bs[b_row][b_col + 6] = f2tf32(bv1.z);
        Bs[b_row][b_col + 7] = f2tf32(bv1.w);
        __syncthreads();

#pragma unroll
        for (int kk = 0; kk < 16; kk += 8) {
            uint32_t af[4][4], bf[4][2];
#pragma unroll
            for (int t = 0; t < 4; t++) {
                int m = wm + t * 16 + r;
                af[t][0] = As[kk + cq][m];
                af[t][1] = As[kk + cq][m + 8];
                af[t][2] = As[kk + cq + 4][m];
                af[t][3] = As[kk + cq + 4][m + 8];
            }
#pragma unroll
            for (int u = 0; u < 4; u++) {
                int n = wn + u * 8 + r;
                bf[u][0] = Bs[kk + cq][n];
                bf[u][1] = Bs[kk + cq + 4][n];
            }
#pragma unroll
            for (int t = 0; t < 4; t++)
#pragma unroll
                for (int u = 0; u < 4; u++)
                    mma_tf32(acc[t][u], af[t], bf[u]);
        }
        __syncthreads();
    }

#pragma unroll
    for (int t = 0; t < 4; t++) {
        int row_a = row0 + wm + t * 16 + r;
#pragma unroll
        for (int u = 0; u < 4; u++) {
            int col = col0 + wn + u * 8 + cq * 2;
            float b0 = bias[col], b1 = bias[col + 1];
            float2 v0 = {acc[t][u][0] + b0, acc[t][u][1] + b1};
            float2 v1 = {acc[t][u][2] + b0, acc[t][u][3] + b1};
            *(float2*)(C + (size_t)row_a * N + col) = v0;
            *(float2*)(C + (size_t)(row_a + 8) * N + col) = v1;
        }
    }
}

// ---------------------------------------------------------------------------
// Grouped g1 (tf32): BM=32, BN=128(=RR), K=HH. Expert = blockIdx.z.
// h1[row,:] = x[row,:] @ W_g1[l,g] + b_g1[l,g]
// 8 warps, each 32x16 (t in 0..1 m16-tiles, u in 0..1 n8-tiles).
// ---------------------------------------------------------------------------
#define PAD1 40
__global__ __launch_bounds__(256)
void tgemm_g1(const float* __restrict__ Wg1, int l)
{
    const int g = blockIdx.z;
    const int cnt = g_cnt[g];
    const int mbase = blockIdx.y * 32;
    if (mbase >= cnt) return;
    const int* rows = g_rows + g * BB;

    const float* Bm = Wg1 + ((size_t)(l * GG + g)) * HH * RR;
    const float* bslice = g_bg1_ptr + (size_t)(l * GG + g) * RR;

    __shared__ uint32_t As[16][PAD1];
    __shared__ uint32_t Bs[16][PADD];
    const int tid = threadIdx.x;
    const int lane = tid & 31, wid = tid >> 5;
    const int wn = wid * 16;
    const int r = lane >> 2, cq = lane & 3;

    const int a_row = tid >> 3, a_col = (tid & 7) * 2;
    const int b_row = tid >> 4, b_col = (tid & 15) * 8;

    int lr = mbase + a_row;
    int src_row = rows[lr < cnt ? lr : (cnt - 1)];
    const float* xrow = g_x + (size_t)src_row * HH;

    float acc[2][2][4];
#pragma unroll
    for (int t = 0; t < 2; t++)
#pragma unroll
        for (int u = 0; u < 2; u++)
#pragma unroll
            for (int v = 0; v < 4; v++) acc[t][u][v] = 0.0f;

    for (int k0 = 0; k0 < HH; k0 += 16) {
        float2 av = *(const float2*)(xrow + k0 + a_col);
        As[a_col + 0][a_row] = f2tf32(av.x);
        As[a_col + 1][a_row] = f2tf32(av.y);

        const float* bp = Bm + (size_t)(k0 + b_row) * RR + b_col;
        float4 bv0 = *(const float4*)bp;
        float4 bv1 = *(const float4*)(bp + 4);
        Bs[b_row][b_col + 0] = f2tf32(bv0.x);
        Bs[b_row][b_col + 1] = f2tf32(bv0.y);
        Bs[b_row][b_col + 2] = f2tf32(bv0.z);
        Bs[b_row][b_col + 3] = f2tf32(bv0.w);
        Bs[b_row][b_col + 4] = f2tf32(bv1.x);
        Bs[b_row][b_col + 5] = f2tf32(bv1.y);
        Bs[b_row][b_col + 6] = f2tf32(bv1.z);
        Bs[b_row][b_col + 7] = f2tf32(bv1.w);
        __syncthreads();

#pragma unroll
        for (int kk = 0; kk < 16; kk += 8) {
            uint32_t af[2][4], bf[2][2];
#pragma unroll
            for (int t = 0; t < 2; t++) {
                int m = t * 16 + r;
                af[t][0] = As[kk + cq][m];
                af[t][1] = As[kk + cq][m + 8];
                af[t][2] = As[kk + cq + 4][m];
                af[t][3] = As[kk + cq + 4][m + 8];
            }
#pragma unroll
            for (int u = 0; u < 2; u++) {
                int n = wn + u * 8 + r;
                bf[u][0] = Bs[kk + cq][n];
                bf[u][1] = Bs[kk + cq + 4][n];
            }
#pragma unroll
            for (int t = 0; t < 2; t++)
#pragma unroll
                for (int u = 0; u < 2; u++)
                    mma_tf32(acc[t][u], af[t], bf[u]);
        }
        __syncthreads();
    }

#pragma unroll
    for (int t = 0; t < 2; t++) {
        int lr0 = mbase + t * 16 + r;
#pragma unroll
        for (int u = 0; u < 2; u++) {
            int col = wn + u * 8 + cq * 2;
            float b0 = bslice[col], b1 = bslice[col + 1];
            if (lr0 < cnt) {
                int row = rows[lr0];
                float2 v = {acc[t][u][0] + b0, acc[t][u][1] + b1};
                *(float2*)(g_h1 + (size_t)row * RR + col) = v;
            }
            if (lr0 + 8 < cnt) {
                int row = rows[lr0 + 8];
                float2 v = {acc[t][u][2] + b0, acc[t][u][3] + b1};
                *(float2*)(g_h1 + (size_t)row * RR + col) = v;
            }
        }
    }
}

// ---------------------------------------------------------------------------
// Grouped g2 + fused ELU (tf32): BM=128, BN=128, K=RR=128.
// x_next[row,c] = elu(y[row,c] + h1[row,:]@W_g2[l,g][:,c] + b_g2[l,g,c])
// ---------------------------------------------------------------------------
__global__ __launch_bounds__(256)
void tgemm_g2(const float* __restrict__ Wg2, const float* __restrict__ bg2,
              int l)
{
    const int g = blockIdx.z;
    const int cnt = g_cnt[g];
    const int mbase = blockIdx.y * 128;
    if (mbase >= cnt) return;
    const int* rows = g_rows + g * BB;
    const int col0 = blockIdx.x * 128;

    const float* Bm   = Wg2 + ((size_t)(l * GG + g)) * RR * HH;
    const float* bias = bg2 + (size_t)(l * GG + g) * HH;

    __shared__ uint32_t As[16][PADD];
    __shared__ uint32_t Bs[16][PADD];
    const int tid = threadIdx.x;
    const int lane = tid & 31, wid = tid >> 5;
    const int wm = (wid & 1) * 64;
    const int wn = (wid >> 1) * 32;
    const int r = lane >> 2, cq = lane & 3;

    const int a_row = tid >> 1, a_col = (tid & 1) * 8;
    const int b_row = tid >> 4, b_col = (tid & 15) * 8;

    int lr = mbase + a_row;
    int src_row = rows[lr < cnt ? lr : (cnt - 1)];
    const float* hrow = g_h1 + (size_t)src_row * RR;

    float acc[4][4][4];
#pragma unroll
    for (int t = 0; t < 4; t++)
#pragma unroll
        for (int u = 0; u < 4; u++)
#pragma unroll
            for (int v = 0; v < 4; v++) acc[t][u][v] = 0.0f;

    for (int k0 = 0; k0 < RR; k0 += 16) {
        const float* ap = hrow + k0 + a_col;
        float4 av0 = *(const float4*)ap;
        float4 av1 = *(const float4*)(ap + 4);
        As[a_col + 0][a_row] = f2tf32(av0.x);
        As[a_col + 1][a_row] = f2tf32(av0.y);
        As[a_col + 2][a_row] = f2tf32(av0.z);
        As[a_col + 3][a_row] = f2tf32(av0.w);
        As[a_col + 4][a_row] = f2tf32(av1.x);
        As[a_col + 5][a_row] = f2tf32(av1.y);
        As[a_col + 6][a_row] = f2tf32(av1.z);
        As[a_col + 7][a_row] = f2tf32(av1.w);

        const float* bp = Bm + (size_t)(k0 + b_row) * HH + col0 + b_col;
        float4 bv0 = *(const float4*)bp;
        float4 bv1 = *(const float4*)(bp + 4);
        Bs[b_row][b_col + 0] = f2tf32(bv0.x);
        Bs[b_row][b_col + 1] = f2tf32(bv0.y);
        Bs[b_row][b_col + 2] = f2tf32(bv0.z);
        Bs[b_row][b_col + 3] = f2tf32(bv0.w);
        Bs[b_row][b_col + 4] = f2tf32(bv1.x);
        Bs[b_row][b_col + 5] = f2tf32(bv1.y);
        Bs[b_row][b_col + 6] = f2tf32(bv1.z);
        Bs[b_row][b_col + 7] = f2tf32(bv1.w);
        __syncthreads();

#pragma unroll
        for (int kk = 0; kk < 16; kk += 8) {
            uint32_t af[4][4], bf[4][2];
#pragma unroll
            for (int t = 0; t < 4; t++) {
                int m = wm + t * 16 + r;
                af[t][0] = As[kk + cq][m];
                af[t][1] = As[kk + cq][m + 8];
                af[t][2] = As[kk + cq + 4][m];
                af[t][3] = As[kk + cq + 4][m + 8];
            }
#pragma unroll
            for (int u = 0; u < 4; u++) {
                int n = wn + u * 8 + r;
                bf[u][0] = Bs[kk + cq][n];
                bf[u][1] = Bs[kk + cq + 4][n];
            }
#pragma unroll
            for (int t = 0; t < 4; t++)
#pragma unroll
                for (int u = 0; u < 4; u++)
                    mma_tf32(acc[t][u], af[t], bf[u]);
        }
        __syncthreads();
    }

#pragma unroll
    for (int t = 0; t < 4; t++) {
        int lr0 = mbase + wm + t * 16 + r;
#pragma unroll
        for (int u = 0; u < 4; u++) {
            int col = col0 + wn + u * 8 + cq * 2;
            float b0 = bias[col], b1 = bias[col + 1];
            if (lr0 < cnt) {
                int row = rows[lr0];
                const float* yp = g_y + (size_t)row * HH + col;
                float2 v = {elu1(yp[0] + acc[t][u][0] + b0),
                            elu1(yp[1] + acc[t][u][1] + b1)};
                *(float2*)(g_x + (size_t)row * HH + col) = v;
            }
            if (lr0 + 8 < cnt) {
                int row = rows[lr0 + 8];
                const float* yp = g_y + (size_t)row * HH + col;
                float2 v = {elu1(yp[0] + acc[t][u][2] + b0),
                            elu1(yp[1] + acc[t][u][3] + b1)};
                *(float2*)(g_x + (size_t)row * HH + col) = v;
            }
        }
    }
}

// ---------------------------------------------------------------------------
// Output GEMM (fp32 SIMT, tiny): out[M,64] = A[M,K]@W[K,64] + bias
// ---------------------------------------------------------------------------
__global__ __launch_bounds__(256, 2)
void sgemm_out(const float* __restrict__ A, const float* __restrict__ W,
               const float* __restrict__ bias, float* __restrict__ C, int K)
{
    __shared__ __align__(16) float As[8][128];
    __shared__ __align__(16) float Bs[8][64];
    const int tid = threadIdx.x;
    const int tx = tid & 15, ty = tid >> 4;
    const int row0 = blockIdx.y * 128;

    const int a_row = tid >> 1;
    const int a_col = (tid & 1) * 4;

    float acc[8][4];
#pragma unroll
    for (int i = 0; i < 8; i++)
#pragma unroll
        for (int j = 0; j < 4; j++) acc[i][j] = 0.0f;

    for (int k0 = 0; k0 < K; k0 += 8) {
        float4 av = *(const float4*)(A + (size_t)(row0 + a_row) * K + k0 + a_col);
        As[a_col + 0][a_row] = av.x;
        As[a_col + 1][a_row] = av.y;
        As[a_col + 2][a_row] = av.z;
        As[a_col + 3][a_row] = av.w;
        if (tid < 128) {
            int br = tid >> 4, bc = (tid & 15) * 4;
            *(float4*)(&Bs[br][bc]) =
                *(const float4*)(W + (size_t)(k0 + br) * AA + bc);
        }
        __syncthreads();
#pragma unroll
        for (int k = 0; k < 8; k++) {
            float4 a0 = *(const float4*)(&As[k][ty * 8]);
            float4 a1 = *(const float4*)(&As[k][ty * 8 + 4]);
            float4 b0 = *(const float4*)(&Bs[k][tx * 4]);
            float ar[8] = {a0.x, a0.y, a0.z, a0.w, a1.x, a1.y, a1.z, a1.w};
            float br4[4] = {b0.x, b0.y, b0.z, b0.w};
#pragma unroll
            for (int i = 0; i < 8; i++)
#pragma unroll
                for (int j = 0; j < 4; j++) acc[i][j] = fmaf(ar[i], br4[j], acc[i][j]);
        }
        __syncthreads();
    }

    const int c = tx * 4;
    float4 bv = *(const float4*)(bias + c);
#pragma unroll
    for (int i = 0; i < 8; i++) {
        int r = row0 + ty * 8 + i;
        float4 v;
        v.x = acc[i][0] + bv.x;
        v.y = acc[i][1] + bv.y;
        v.z = acc[i][2] + bv.z;
        v.w = acc[i][3] + bv.w;
        *(float4*)(C + (size_t)r * AA + c) = v;
    }
}

// ---------------------------------------------------------------------------
// Launch — inputs classified by size (permutation-independent).
// ---------------------------------------------------------------------------
extern "C" void kernel_launch(void* const* d_in, const int* in_sizes, int n_in,
                              void* d_out, int out_size)
{
    const float* s = 0; const float* W_in = 0; const float* b_in = 0;
    const float* W_main = 0; const float* b_main = 0; const float* b_g2 = 0;
    const float* W_out = 0; const float* b_out = 0;
    const float* w8[2] = {0, 0};
    const void*  c4[2] = {0, 0};
    int n8 = 0, n4 = 0;

    for (int i = 0; i < n_in; i++) {
        switch (in_sizes[i]) {
            case 2097152:  s      = (const float*)d_in[i]; break;
            case 1048576:  W_in   = (const float*)d_in[i]; break;
            case 2048:     b_in   = (const float*)d_in[i]; break;
            case 16777216: W_main = (const float*)d_in[i]; break;
            case 8192:     b_main = (const float*)d_in[i]; break;
            case 65536:    b_g2   = (const float*)d_in[i]; break;
            case 131072:   W_out  = (const float*)d_in[i]; break;
            case 64:       b_out  = (const float*)d_in[i]; break;
            case 8388608:  if (n8 < 2) w8[n8++] = (const float*)d_in[i]; break;
            case 4096:     if (n4 < 2) c4[n4++] = d_in[i]; break;
            default: break;
        }
    }
    const float* W_g1 = w8[0];
    const float* W_g2 = w8[1];
    float* out = (float*)d_out;

    float* x_ptr;  cudaGetSymbolAddress((void**)&x_ptr, g_x);
    float* y_ptr;  cudaGetSymbolAddress((void**)&y_ptr, g_y);

    dim3 blk(256);

    build_routing<<<1, 256>>>((const int*)c4[0], (const int*)c4[1]);

    // x = s @ W_in + b_in   [4096,512]x[512,2048]
    tgemm_bias<<<dim3(HH / 128, BB / 128), blk>>>(s, W_in, b_in, x_ptr, BB, HH, SS);

    for (int l = 0; l < LL; l++) {
        tgemm_bias<<<dim3(HH / 128, BB / 128), blk>>>(
            x_ptr, W_main + (size_t)l * HH * HH, b_main + (size_t)l * HH,
            y_ptr, BB, HH, HH);
        tgemm_g1<<<dim3(1, BB / 32, GG), blk>>>(W_g1, l);
        tgemm_g2<<<dim3(HH / 128, BB / 128, GG), blk>>>(W_g2, b_g2, l);
    }

    // out = x @ W_out + b_out   [4096,2048]x[2048,64]
    sgemm_out<<<dim3(1, BB / 128), blk>>>(x_ptr, W_out, b_out, out, HH);
}

// round 6
// speedup vs baseline: 3.0319x; 1.2351x over previous
#include <cuda_runtime.h>
#include <math.h>
#include <stdint.h>

// Problem constants  (L,G,H,R,S,A,B = 4,8,2048,128,512,64,4096)
#define BB 4096
#define SS 512
#define HH 2048
#define RR 128
#define AA 64
#define GG 8
#define LL 4

// Scratch
__device__ __align__(16) float g_x[(size_t)BB * HH];
__device__ __align__(16) float g_y[(size_t)BB * HH];
__device__ __align__(16) float g_h1[(size_t)BB * RR];
__device__ int g_cnt[GG];
__device__ int g_rows[GG * BB];
__device__ const float* g_bg1_ptr;

// ---------------------------------------------------------------------------
// helpers
// ---------------------------------------------------------------------------
__device__ __forceinline__ uint32_t f2tf32(float v) {
    uint32_t u;
    asm("cvt.rna.tf32.f32 %0, %1;" : "=r"(u) : "f"(v));
    return u;
}
__device__ __forceinline__ void mma_tf32(float* d, const uint32_t* a,
                                         const uint32_t* b) {
    asm volatile(
        "mma.sync.aligned.m16n8k8.row.col.f32.tf32.tf32.f32 "
        "{%0,%1,%2,%3}, {%4,%5,%6,%7}, {%8,%9}, {%0,%1,%2,%3};"
        : "+f"(d[0]), "+f"(d[1]), "+f"(d[2]), "+f"(d[3])
        : "r"(a[0]), "r"(a[1]), "r"(a[2]), "r"(a[3]), "r"(b[0]), "r"(b[1]));
}
__device__ __forceinline__ float elu1(float v) {
    return v > 0.0f ? v : expm1f(v);
}
__device__ __forceinline__ void cp16(uint32_t s, const void* g) {
    asm volatile("cp.async.ca.shared.global [%0], [%1], 16;" :: "r"(s), "l"(g));
}
#define CP_COMMIT() asm volatile("cp.async.commit_group;")
#define CP_WAIT1()  asm volatile("cp.async.wait_group 1;")
#define CP_WAIT0()  asm volatile("cp.async.wait_group 0;")

// smem layout strides (floats)
#define ASTRIDE 36     // A tiles [m][k] k-extent 32, pad->36 (conflict-free)
#define BSTRIDE 136    // B tiles [k][n] n-extent 128, pad->136 (conflict-free)
#define A_ST (128 * ASTRIDE)   // per-stage A floats (BM=128)
#define B_ST (32 * BSTRIDE)    // per-stage B floats (BK=32)
#define A_ST1 (32 * ASTRIDE)   // per-stage A floats (BM=32, g1)

// ---------------------------------------------------------------------------
// Routing (also resolves the {o, b_g1} size-4096 ambiguity by content)
// ---------------------------------------------------------------------------
__global__ void build_routing(const int* __restrict__ c0,
                              const int* __restrict__ c1)
{
    __shared__ const int* o_ptr;
    __shared__ int stride;
    int tid = threadIdx.x;
    if (tid == 0) {
        const int* cands[2] = {c0, c1};
        int pick = 0; stride = 1;
        for (int c = 0; c < 2; c++) {
            const int* p = cands[c];
            bool ok32 = true, nz32 = false;
            for (int i = 0; i < 256; i++) {
                int v = p[i];
                if (v < 0 || v >= GG) { ok32 = false; break; }
                if (v) nz32 = true;
            }
            if (ok32 && nz32) { pick = c; stride = 1; break; }
            bool ok64 = true, nz64 = false;
            for (int i = 0; i < 256; i++) {
                int lo = p[2 * i], hi = p[2 * i + 1];
                if (hi != 0 || lo < 0 || lo >= GG) { ok64 = false; break; }
                if (lo) nz64 = true;
            }
            if (ok64 && nz64) { pick = c; stride = 2; break; }
        }
        o_ptr = cands[pick];
        g_bg1_ptr = (const float*)cands[1 - pick];
    }
    if (tid < GG) g_cnt[tid] = 0;
    __syncthreads();
    const int* o = o_ptr;
    const int st = stride;
    for (int b = tid; b < BB; b += blockDim.x) {
        int e = o[(size_t)b * st];
        int idx = atomicAdd(&g_cnt[e], 1);
        g_rows[e * BB + idx] = b;
    }
}

// ---------------------------------------------------------------------------
// Dense tf32 GEMM, 2-stage cp.async pipeline.
// C[M,N] = A[M,K] @ B[K,N] + bias.  BM=BN=128, BK=32, 256 thr (8 warps 64x32).
// ---------------------------------------------------------------------------
__global__ __launch_bounds__(256)
void tgemm_bias(const float* __restrict__ A, const float* __restrict__ Bm,
                const float* __restrict__ bias, float* __restrict__ C,
                int M, int N, int K)
{
    extern __shared__ float sm[];
    float* As = sm;                    // [2][128][36]
    float* Bs = sm + 2 * A_ST;         // [2][32][136]
    const uint32_t sA = (uint32_t)__cvta_generic_to_shared(As);
    const uint32_t sB = (uint32_t)__cvta_generic_to_shared(Bs);

    const int tid = threadIdx.x;
    const int lane = tid & 31, wid = tid >> 5;
    const int wm = (wid & 1) * 64, wn = (wid >> 1) * 32;
    const int row0 = blockIdx.y * 128, col0 = blockIdx.x * 128;
    const int r = lane >> 2, cq = lane & 3;

    float acc[4][4][4];
#pragma unroll
    for (int t = 0; t < 4; t++)
#pragma unroll
        for (int u = 0; u < 4; u++)
#pragma unroll
            for (int v = 0; v < 4; v++) acc[t][u][v] = 0.0f;

    const int NT = K >> 5;

    // tile loader
    auto load_tile = [&](int st, int k0) {
#pragma unroll
        for (int i = 0; i < 4; i++) {
            int cc = tid + i * 256;
            int m = cc >> 3, kc = (cc & 7) * 4;
            cp16(sA + (st * A_ST + m * ASTRIDE + kc) * 4,
                 A + (size_t)(row0 + m) * K + k0 + kc);
        }
#pragma unroll
        for (int i = 0; i < 4; i++) {
            int cc = tid + i * 256;
            int kr = cc >> 5, nc = (cc & 31) * 4;
            cp16(sB + (st * B_ST + kr * BSTRIDE + nc) * 4,
                 Bm + (size_t)(k0 + kr) * N + col0 + nc);
        }
    };

    load_tile(0, 0);
    CP_COMMIT();

    for (int kt = 0; kt < NT; kt++) {
        if (kt + 1 < NT) {
            load_tile((kt + 1) & 1, (kt + 1) << 5);
            CP_COMMIT();
            CP_WAIT1();
        } else {
            CP_WAIT0();
        }
        __syncthreads();

        const float* Ab = As + (kt & 1) * A_ST;
        const float* Bb = Bs + (kt & 1) * B_ST;
#pragma unroll
        for (int kk = 0; kk < 32; kk += 8) {
            uint32_t af[4][4], bf[4][2];
#pragma unroll
            for (int t = 0; t < 4; t++) {
                int m = wm + t * 16 + r;
                af[t][0] = f2tf32(Ab[m * ASTRIDE + kk + cq]);
                af[t][1] = f2tf32(Ab[(m + 8) * ASTRIDE + kk + cq]);
                af[t][2] = f2tf32(Ab[m * ASTRIDE + kk + cq + 4]);
                af[t][3] = f2tf32(Ab[(m + 8) * ASTRIDE + kk + cq + 4]);
            }
#pragma unroll
            for (int u = 0; u < 4; u++) {
                int n = wn + u * 8 + r;
                bf[u][0] = f2tf32(Bb[(kk + cq) * BSTRIDE + n]);
                bf[u][1] = f2tf32(Bb[(kk + cq + 4) * BSTRIDE + n]);
            }
#pragma unroll
            for (int t = 0; t < 4; t++)
#pragma unroll
                for (int u = 0; u < 4; u++)
                    mma_tf32(acc[t][u], af[t], bf[u]);
        }
        __syncthreads();
    }

#pragma unroll
    for (int t = 0; t < 4; t++) {
        int row_a = row0 + wm + t * 16 + r;
#pragma unroll
        for (int u = 0; u < 4; u++) {
            int col = col0 + wn + u * 8 + cq * 2;
            float b0 = bias[col], b1 = bias[col + 1];
            float2 v0 = {acc[t][u][0] + b0, acc[t][u][1] + b1};
            float2 v1 = {acc[t][u][2] + b0, acc[t][u][3] + b1};
            *(float2*)(C + (size_t)row_a * N + col) = v0;
            *(float2*)(C + (size_t)(row_a + 8) * N + col) = v1;
        }
    }
}

// ---------------------------------------------------------------------------
// Grouped g1 (tf32, pipelined): BM=32, BN=128(=RR), K=HH, BK=32.
// h1[row,:] = x[row,:] @ W_g1[l,g] + b_g1[l,g].  8 warps, each 32x16.
// ---------------------------------------------------------------------------
__global__ __launch_bounds__(256)
void tgemm_g1(const float* __restrict__ Wg1, int l)
{
    const int g = blockIdx.z;
    const int cnt = g_cnt[g];
    const int mbase = blockIdx.y * 32;
    if (mbase >= cnt) return;
    const int* rows = g_rows + g * BB;

    const float* Bm = Wg1 + ((size_t)(l * GG + g)) * HH * RR;
    const float* bslice = g_bg1_ptr + (size_t)(l * GG + g) * RR;

    extern __shared__ float sm[];
    float* As = sm;                      // [2][32][36]
    float* Bs = sm + 2 * A_ST1;          // [2][32][136]
    int* rows_s = (int*)(sm + 2 * A_ST1 + 2 * B_ST);  // [32]
    const uint32_t sA = (uint32_t)__cvta_generic_to_shared(As);
    const uint32_t sB = (uint32_t)__cvta_generic_to_shared(Bs);

    const int tid = threadIdx.x;
    const int lane = tid & 31, wid = tid >> 5;
    const int wn = wid * 16;
    const int r = lane >> 2, cq = lane & 3;

    if (tid < 32) {
        int lr = mbase + tid;
        rows_s[tid] = rows[lr < cnt ? lr : (cnt - 1)];
    }
    __syncthreads();

    float acc[2][2][4];
#pragma unroll
    for (int t = 0; t < 2; t++)
#pragma unroll
        for (int u = 0; u < 2; u++)
#pragma unroll
            for (int v = 0; v < 4; v++) acc[t][u][v] = 0.0f;

    const int NT = HH >> 5;   // 64

    auto load_tile = [&](int st, int k0) {
        if (tid < 256) {
            int m = tid >> 3, kc = (tid & 7) * 4;
            cp16(sA + (st * A_ST1 + m * ASTRIDE + kc) * 4,
                 g_x + (size_t)rows_s[m] * HH + k0 + kc);
        }
#pragma unroll
        for (int i = 0; i < 4; i++) {
            int cc = tid + i * 256;
            int kr = cc >> 5, nc = (cc & 31) * 4;
            cp16(sB + (st * B_ST + kr * BSTRIDE + nc) * 4,
                 Bm + (size_t)(k0 + kr) * RR + nc);
        }
    };

    load_tile(0, 0);
    CP_COMMIT();

    for (int kt = 0; kt < NT; kt++) {
        if (kt + 1 < NT) {
            load_tile((kt + 1) & 1, (kt + 1) << 5);
            CP_COMMIT();
            CP_WAIT1();
        } else {
            CP_WAIT0();
        }
        __syncthreads();

        const float* Ab = As + (kt & 1) * A_ST1;
        const float* Bb = Bs + (kt & 1) * B_ST;
#pragma unroll
        for (int kk = 0; kk < 32; kk += 8) {
            uint32_t af[2][4], bf[2][2];
#pragma unroll
            for (int t = 0; t < 2; t++) {
                int m = t * 16 + r;
                af[t][0] = f2tf32(Ab[m * ASTRIDE + kk + cq]);
                af[t][1] = f2tf32(Ab[(m + 8) * ASTRIDE + kk + cq]);
                af[t][2] = f2tf32(Ab[m * ASTRIDE + kk + cq + 4]);
                af[t][3] = f2tf32(Ab[(m + 8) * ASTRIDE + kk + cq + 4]);
            }
#pragma unroll
            for (int u = 0; u < 2; u++) {
                int n = wn + u * 8 + r;
                bf[u][0] = f2tf32(Bb[(kk + cq) * BSTRIDE + n]);
                bf[u][1] = f2tf32(Bb[(kk + cq + 4) * BSTRIDE + n]);
            }
#pragma unroll
            for (int t = 0; t < 2; t++)
#pragma unroll
                for (int u = 0; u < 2; u++)
                    mma_tf32(acc[t][u], af[t], bf[u]);
        }
        __syncthreads();
    }

#pragma unroll
    for (int t = 0; t < 2; t++) {
        int lr0 = mbase + t * 16 + r;
#pragma unroll
        for (int u = 0; u < 2; u++) {
            int col = wn + u * 8 + cq * 2;
            float b0 = bslice[col], b1 = bslice[col + 1];
            if (lr0 < cnt) {
                int row = rows[lr0];
                float2 v = {acc[t][u][0] + b0, acc[t][u][1] + b1};
                *(float2*)(g_h1 + (size_t)row * RR + col) = v;
            }
            if (lr0 + 8 < cnt) {
                int row = rows[lr0 + 8];
                float2 v = {acc[t][u][2] + b0, acc[t][u][3] + b1};
                *(float2*)(g_h1 + (size_t)row * RR + col) = v;
            }
        }
    }
}

// ---------------------------------------------------------------------------
// Grouped g2 + fused ELU (tf32, pipelined): BM=128, BN=128, K=RR=128, BK=32.
// x_next[row,c] = elu(y[row,c] + h1[row,:]@W_g2[l,g][:,c] + b_g2[l,g,c])
// ---------------------------------------------------------------------------
__global__ __launch_bounds__(256)
void tgemm_g2(const float* __restrict__ Wg2, const float* __restrict__ bg2,
              int l)
{
    const int g = blockIdx.z;
    const int cnt = g_cnt[g];
    const int mbase = blockIdx.y * 128;
    if (mbase >= cnt) return;
    const int* rows = g_rows + g * BB;
    const int col0 = blockIdx.x * 128;

    const float* Bm   = Wg2 + ((size_t)(l * GG + g)) * RR * HH;
    const float* bias = bg2 + (size_t)(l * GG + g) * HH;

    extern __shared__ float sm[];
    float* As = sm;                     // [2][128][36]
    float* Bs = sm + 2 * A_ST;          // [2][32][136]
    int* rows_s = (int*)(sm + 2 * A_ST + 2 * B_ST);   // [128]
    const uint32_t sA = (uint32_t)__cvta_generic_to_shared(As);
    const uint32_t sB = (uint32_t)__cvta_generic_to_shared(Bs);

    const int tid = threadIdx.x;
    const int lane = tid & 31, wid = tid >> 5;
    const int wm = (wid & 1) * 64, wn = (wid >> 1) * 32;
    const int r = lane >> 2, cq = lane & 3;

    if (tid < 128) {
        int lr = mbase + tid;
        rows_s[tid] = rows[lr < cnt ? lr : (cnt - 1)];
    }
    __syncthreads();

    float acc[4][4][4];
#pragma unroll
    for (int t = 0; t < 4; t++)
#pragma unroll
        for (int u = 0; u < 4; u++)
#pragma unroll
            for (int v = 0; v < 4; v++) acc[t][u][v] = 0.0f;

    const int NT = RR >> 5;   // 4

    auto load_tile = [&](int st, int k0) {
#pragma unroll
        for (int i = 0; i < 4; i++) {
            int cc = tid + i * 256;
            int m = cc >> 3, kc = (cc & 7) * 4;
            cp16(sA + (st * A_ST + m * ASTRIDE + kc) * 4,
                 g_h1 + (size_t)rows_s[m] * RR + k0 + kc);
        }
#pragma unroll
        for (int i = 0; i < 4; i++) {
            int cc = tid + i * 256;
            int kr = cc >> 5, nc = (cc & 31) * 4;
            cp16(sB + (st * B_ST + kr * BSTRIDE + nc) * 4,
                 Bm + (size_t)(k0 + kr) * HH + col0 + nc);
        }
    };

    load_tile(0, 0);
    CP_COMMIT();

    for (int kt = 0; kt < NT; kt++) {
        if (kt + 1 < NT) {
            load_tile((kt + 1) & 1, (kt + 1) << 5);
            CP_COMMIT();
            CP_WAIT1();
        } else {
            CP_WAIT0();
        }
        __syncthreads();

        const float* Ab = As + (kt & 1) * A_ST;
        const float* Bb = Bs + (kt & 1) * B_ST;
#pragma unroll
        for (int kk = 0; kk < 32; kk += 8) {
            uint32_t af[4][4], bf[4][2];
#pragma unroll
            for (int t = 0; t < 4; t++) {
                int m = wm + t * 16 + r;
                af[t][0] = f2tf32(Ab[m * ASTRIDE + kk + cq]);
                af[t][1] = f2tf32(Ab[(m + 8) * ASTRIDE + kk + cq]);
                af[t][2] = f2tf32(Ab[m * ASTRIDE + kk + cq + 4]);
                af[t][3] = f2tf32(Ab[(m + 8) * ASTRIDE + kk + cq + 4]);
            }
#pragma unroll
            for (int u = 0; u < 4; u++) {
                int n = wn + u * 8 + r;
                bf[u][0] = f2tf32(Bb[(kk + cq) * BSTRIDE + n]);
                bf[u][1] = f2tf32(Bb[(kk + cq + 4) * BSTRIDE + n]);
            }
#pragma unroll
            for (int t = 0; t < 4; t++)
#pragma unroll
                for (int u = 0; u < 4; u++)
                    mma_tf32(acc[t][u], af[t], bf[u]);
        }
        __syncthreads();
    }

#pragma unroll
    for (int t = 0; t < 4; t++) {
        int lr0 = mbase + wm + t * 16 + r;
#pragma unroll
        for (int u = 0; u < 4; u++) {
            int col = col0 + wn + u * 8 + cq * 2;
            float b0 = bias[col], b1 = bias[col + 1];
            if (lr0 < cnt) {
                int row = rows[lr0];
                const float* yp = g_y + (size_t)row * HH + col;
                float2 v = {elu1(yp[0] + acc[t][u][0] + b0),
                            elu1(yp[1] + acc[t][u][1] + b1)};
                *(float2*)(g_x + (size_t)row * HH + col) = v;
            }
            if (lr0 + 8 < cnt) {
                int row = rows[lr0 + 8];
                const float* yp = g_y + (size_t)row * HH + col;
                float2 v = {elu1(yp[0] + acc[t][u][2] + b0),
                            elu1(yp[1] + acc[t][u][3] + b1)};
                *(float2*)(g_x + (size_t)row * HH + col) = v;
            }
        }
    }
}

// ---------------------------------------------------------------------------
// Output GEMM (fp32 SIMT, tiny): out[M,64] = A[M,K]@W[K,64] + bias
// ---------------------------------------------------------------------------
__global__ __launch_bounds__(256, 2)
void sgemm_out(const float* __restrict__ A, const float* __restrict__ W,
               const float* __restrict__ bias, float* __restrict__ C, int K)
{
    __shared__ __align__(16) float As2[8][128];
    __shared__ __align__(16) float Bs2[8][64];
    const int tid = threadIdx.x;
    const int tx = tid & 15, ty = tid >> 4;
    const int row0 = blockIdx.y * 128;

    const int a_row = tid >> 1;
    const int a_col = (tid & 1) * 4;

    float acc[8][4];
#pragma unroll
    for (int i = 0; i < 8; i++)
#pragma unroll
        for (int j = 0; j < 4; j++) acc[i][j] = 0.0f;

    for (int k0 = 0; k0 < K; k0 += 8) {
        float4 av = *(const float4*)(A + (size_t)(row0 + a_row) * K + k0 + a_col);
        As2[a_col + 0][a_row] = av.x;
        As2[a_col + 1][a_row] = av.y;
        As2[a_col + 2][a_row] = av.z;
        As2[a_col + 3][a_row] = av.w;
        if (tid < 128) {
            int br = tid >> 4, bc = (tid & 15) * 4;
            *(float4*)(&Bs2[br][bc]) =
                *(const float4*)(W + (size_t)(k0 + br) * AA + bc);
        }
        __syncthreads();
#pragma unroll
        for (int k = 0; k < 8; k++) {
            float4 a0 = *(const float4*)(&As2[k][ty * 8]);
            float4 a1 = *(const float4*)(&As2[k][ty * 8 + 4]);
            float4 b0 = *(const float4*)(&Bs2[k][tx * 4]);
            float ar[8] = {a0.x, a0.y, a0.z, a0.w, a1.x, a1.y, a1.z, a1.w};
            float br4[4] = {b0.x, b0.y, b0.z, b0.w};
#pragma unroll
            for (int i = 0; i < 8; i++)
#pragma unroll
                for (int j = 0; j < 4; j++) acc[i][j] = fmaf(ar[i], br4[j], acc[i][j]);
        }
        __syncthreads();
    }

    const int c = tx * 4;
    float4 bv = *(const float4*)(bias + c);
#pragma unroll
    for (int i = 0; i < 8; i++) {
        int r = row0 + ty * 8 + i;
        float4 v;
        v.x = acc[i][0] + bv.x;
        v.y = acc[i][1] + bv.y;
        v.z = acc[i][2] + bv.z;
        v.w = acc[i][3] + bv.w;
        *(float4*)(C + (size_t)r * AA + c) = v;
    }
}

// ---------------------------------------------------------------------------
// Launch — inputs classified by size (permutation-independent).
// ---------------------------------------------------------------------------
extern "C" void kernel_launch(void* const* d_in, const int* in_sizes, int n_in,
                              void* d_out, int out_size)
{
    const float* s = 0; const float* W_in = 0; const float* b_in = 0;
    const float* W_main = 0; const float* b_main = 0; const float* b_g2 = 0;
    const float* W_out = 0; const float* b_out = 0;
    const float* w8[2] = {0, 0};
    const void*  c4[2] = {0, 0};
    int n8 = 0, n4 = 0;

    for (int i = 0; i < n_in; i++) {
        switch (in_sizes[i]) {
            case 2097152:  s      = (const float*)d_in[i]; break;
            case 1048576:  W_in   = (const float*)d_in[i]; break;
            case 2048:     b_in   = (const float*)d_in[i]; break;
            case 16777216: W_main = (const float*)d_in[i]; break;
            case 8192:     b_main = (const float*)d_in[i]; break;
            case 65536:    b_g2   = (const float*)d_in[i]; break;
            case 131072:   W_out  = (const float*)d_in[i]; break;
            case 64:       b_out  = (const float*)d_in[i]; break;
            case 8388608:  if (n8 < 2) w8[n8++] = (const float*)d_in[i]; break;
            case 4096:     if (n4 < 2) c4[n4++] = d_in[i]; break;
            default: break;
        }
    }
    const float* W_g1 = w8[0];
    const float* W_g2 = w8[1];
    float* out = (float*)d_out;

    float* x_ptr;  cudaGetSymbolAddress((void**)&x_ptr, g_x);
    float* y_ptr;  cudaGetSymbolAddress((void**)&y_ptr, g_y);

    // dynamic smem sizes
    const int smem_big = (2 * A_ST + 2 * B_ST) * 4 + 128 * 4;   // 72192 B
    const int smem_g1  = (2 * A_ST1 + 2 * B_ST) * 4 + 32 * 4;   // 44160 B
    static int attr_done = 0;
    cudaFuncSetAttribute(tgemm_bias, cudaFuncAttributeMaxDynamicSharedMemorySize, smem_big);
    cudaFuncSetAttribute(tgemm_g2,   cudaFuncAttributeMaxDynamicSharedMemorySize, smem_big);
    cudaFuncSetAttribute(tgemm_g1,   cudaFuncAttributeMaxDynamicSharedMemorySize, smem_g1);
    (void)attr_done;

    dim3 blk(256);

    build_routing<<<1, 256>>>((const int*)c4[0], (const int*)c4[1]);

    // x = s @ W_in + b_in   [4096,512]x[512,2048]
    tgemm_bias<<<dim3(HH / 128, BB / 128), blk, smem_big>>>(
        s, W_in, b_in, x_ptr, BB, HH, SS);

    for (int l = 0; l < LL; l++) {
        tgemm_bias<<<dim3(HH / 128, BB / 128), blk, smem_big>>>(
            x_ptr, W_main + (size_t)l * HH * HH, b_main + (size_t)l * HH,
            y_ptr, BB, HH, HH);
        tgemm_g1<<<dim3(1, BB / 32, GG), blk, smem_g1>>>(W_g1, l);
        tgemm_g2<<<dim3(HH / 128, BB / 128, GG), blk, smem_big>>>(W_g2, b_g2, l);
    }

    // out = x @ W_out + b_out   [4096,2048]x[2048,64]
    sgemm_out<<<dim3(1, BB / 128), blk>>>(x_ptr, W_out, b_out, out, HH);
}

// round 7
// speedup vs baseline: 4.1041x; 1.3536x over previous
#include <cuda_runtime.h>
#include <math.h>
#include <stdint.h>

// Problem constants  (L,G,H,R,S,A,B = 4,8,2048,128,512,64,4096)
#define BB 4096
#define SS 512
#define HH 2048
#define RR 128
#define AA 64
#define GG 8
#define LL 4

// ---------------------------------------------------------------------------
// Scratch (device globals)
// ---------------------------------------------------------------------------
__device__ __align__(16) float g_x[(size_t)BB * HH];
__device__ __align__(16) float g_y[(size_t)BB * HH];
__device__ __align__(16) float g_h1[(size_t)BB * RR];
__device__ __align__(16) float g_h1p[4][(size_t)BB * RR];
__device__ __align__(16) float g_outp[8][(size_t)BB * AA];
__device__ __align__(16) float g_Wmt[(size_t)LL * HH * HH];      // W_main^T tf32
__device__ __align__(16) float g_Wg1t[(size_t)LL * GG * HH * RR]; // W_g1^T tf32
__device__ __align__(16) float g_Wg2t[(size_t)LL * GG * RR * HH]; // W_g2^T tf32
__device__ __align__(16) float g_Wint[(size_t)SS * HH];           // W_in^T tf32
__device__ __align__(16) float g_sr[(size_t)BB * SS];             // s tf32
__device__ int g_cnt[GG];
__device__ int g_rows[GG * BB];
__device__ int g_eid[BB];
__device__ const float* g_bg1_ptr;

// ---------------------------------------------------------------------------
// helpers
// ---------------------------------------------------------------------------
__device__ __forceinline__ uint32_t f2tf32(float v) {
    uint32_t u;
    asm("cvt.rna.tf32.f32 %0, %1;" : "=r"(u) : "f"(v));
    return u;
}
__device__ __forceinline__ float rndtf(float v) {
    return __uint_as_float(f2tf32(v));
}
__device__ __forceinline__ void mma_tf32(float* d, const uint32_t* a,
                                         const uint32_t* b) {
    asm volatile(
        "mma.sync.aligned.m16n8k8.row.col.f32.tf32.tf32.f32 "
        "{%0,%1,%2,%3}, {%4,%5,%6,%7}, {%8,%9}, {%0,%1,%2,%3};"
        : "+f"(d[0]), "+f"(d[1]), "+f"(d[2]), "+f"(d[3])
        : "r"(a[0]), "r"(a[1]), "r"(a[2]), "r"(a[3]), "r"(b[0]), "r"(b[1]));
}
__device__ __forceinline__ void ldsm4(uint32_t& r0, uint32_t& r1, uint32_t& r2,
                                      uint32_t& r3, uint32_t addr) {
    asm volatile("ldmatrix.sync.aligned.m8n8.x4.shared.b16 {%0,%1,%2,%3}, [%4];"
                 : "=r"(r0), "=r"(r1), "=r"(r2), "=r"(r3) : "r"(addr));
}
__device__ __forceinline__ float elu1(float v) {
    return v > 0.0f ? v : expm1f(v);
}
__device__ __forceinline__ void cp16(uint32_t s, const void* g) {
    asm volatile("cp.async.ca.shared.global [%0], [%1], 16;" :: "r"(s), "l"(g));
}
#define CP_COMMIT() asm volatile("cp.async.commit_group;")
#define CP_WAITG(n) asm volatile("cp.async.wait_group %0;" :: "n"(n))

#define TSTRIDE 36              // floats per smem row (32 data + 4 pad)
#define STG_A  (128 * TSTRIDE)  // 4608 floats
#define STG    (2 * STG_A)      // per-stage A+B floats (big kernels)
#define G1_A   (32 * TSTRIDE)   // 1152
#define G1_STG (G1_A + 128 * TSTRIDE)  // 5760

// ---------------------------------------------------------------------------
// Routing (resolves {o, b_g1} ambiguity by content) + per-row expert ids
// ---------------------------------------------------------------------------
__global__ void build_routing(const int* __restrict__ c0,
                              const int* __restrict__ c1)
{
    __shared__ const int* o_ptr;
    __shared__ int stride;
    int tid = threadIdx.x;
    if (tid == 0) {
        const int* cands[2] = {c0, c1};
        int pick = 0; stride = 1;
        for (int c = 0; c < 2; c++) {
            const int* p = cands[c];
            bool ok32 = true, nz32 = false;
            for (int i = 0; i < 256; i++) {
                int v = p[i];
                if (v < 0 || v >= GG) { ok32 = false; break; }
                if (v) nz32 = true;
            }
            if (ok32 && nz32) { pick = c; stride = 1; break; }
            bool ok64 = true, nz64 = false;
            for (int i = 0; i < 256; i++) {
                int lo = p[2 * i], hi = p[2 * i + 1];
                if (hi != 0 || lo < 0 || lo >= GG) { ok64 = false; break; }
                if (lo) nz64 = true;
            }
            if (ok64 && nz64) { pick = c; stride = 2; break; }
        }
        o_ptr = cands[pick];
        g_bg1_ptr = (const float*)cands[1 - pick];
    }
    if (tid < GG) g_cnt[tid] = 0;
    __syncthreads();
    const int* o = o_ptr;
    const int st = stride;
    for (int b = tid; b < BB; b += blockDim.x) {
        int e = o[(size_t)b * st];
        g_eid[b] = e;
        int idx = atomicAdd(&g_cnt[e], 1);
        g_rows[e * BB + idx] = b;
    }
}

// ---------------------------------------------------------------------------
// Prep: transpose + tf32-round. src [K][N] (batched) -> dst [N][K].
// ---------------------------------------------------------------------------
__global__ void transpose_rna(const float* __restrict__ src,
                              float* __restrict__ dst, int K, int N)
{
    __shared__ float t[32][33];
    const size_t mb = (size_t)blockIdx.z * K * N;
    int k0 = blockIdx.y * 32, n0 = blockIdx.x * 32;
    int x = threadIdx.x, y = threadIdx.y;  // 32x8
#pragma unroll
    for (int i = y; i < 32; i += 8)
        t[i][x] = src[mb + (size_t)(k0 + i) * N + n0 + x];
    __syncthreads();
#pragma unroll
    for (int i = y; i < 32; i += 8)
        dst[mb + (size_t)(n0 + i) * K + k0 + x] = rndtf(t[x][i]);
}

__global__ void round_s(const float* __restrict__ s)
{
    int idx = (blockIdx.x * 256 + threadIdx.x) * 4;
    float4 v = *(const float4*)(s + idx);
    v.x = rndtf(v.x); v.y = rndtf(v.y); v.z = rndtf(v.z); v.w = rndtf(v.w);
    *(float4*)(g_sr + idx) = v;
}

// ---------------------------------------------------------------------------
// Dense tf32 GEMM with LDSM fragments, inputs pre-rounded to tf32.
// C[M,N] = A[M,K] @ Bt[N,K]^T + bias.  BM=BN=128, BK=32, 256 thr.
// rnd: round output to tf32 (when it feeds another GEMM).
// ---------------------------------------------------------------------------
__global__ __launch_bounds__(256)
void tgemm_t(const float* __restrict__ A, int lda,
             const float* __restrict__ Bt, int ldb,
             const float* __restrict__ bias, float* __restrict__ C,
             int N, int K, int rnd)
{
    extern __shared__ float sm[];
    const int tid = threadIdx.x, lane = tid & 31, wid = tid >> 5;
    const int wm = (wid & 1) * 64, wn = (wid >> 1) * 32;
    const int row0 = blockIdx.y * 128, col0 = blockIdx.x * 128;
    const int r = lane >> 2, cq = lane & 3;
    const uint32_t sbase = (uint32_t)__cvta_generic_to_shared(sm);

    const uint32_t aAddr0 = sbase +
        ((wm + (lane & 15)) * TSTRIDE + ((lane >> 4) << 2)) * 4;
    const uint32_t bAddr0 = sbase + STG_A * 4 +
        ((wn + ((lane >> 4) << 3) + (lane & 7)) * TSTRIDE +
         (((lane >> 3) & 1) << 2)) * 4;

    float acc[4][4][4];
#pragma unroll
    for (int t = 0; t < 4; t++)
#pragma unroll
        for (int u = 0; u < 4; u++)
#pragma unroll
            for (int v = 0; v < 4; v++) acc[t][u][v] = 0.0f;

    const int NT = K >> 5;
    auto load_tile = [&](int st, int k0) {
        const uint32_t sA = sbase + st * STG * 4;
        const uint32_t sB = sA + STG_A * 4;
#pragma unroll
        for (int i = 0; i < 4; i++) {
            int cc = tid + i * 256;
            int m = cc >> 3, kc = (cc & 7) * 4;
            cp16(sA + (m * TSTRIDE + kc) * 4,
                 A + (size_t)(row0 + m) * lda + k0 + kc);
            cp16(sB + (m * TSTRIDE + kc) * 4,
                 Bt + (size_t)(col0 + m) * ldb + k0 + kc);
        }
    };

    load_tile(0, 0);
    CP_COMMIT();
    for (int kt = 0; kt < NT; kt++) {
        if (kt + 1 < NT) load_tile((kt + 1) & 1, (kt + 1) << 5);
        CP_COMMIT();
        CP_WAITG(1);
        __syncthreads();
        const uint32_t off = (kt & 1) * STG * 4;
#pragma unroll
        for (int kk = 0; kk < 32; kk += 8) {
            uint32_t af[4][4], bf[4][2];
#pragma unroll
            for (int t = 0; t < 4; t++)
                ldsm4(af[t][0], af[t][1], af[t][2], af[t][3],
                      aAddr0 + off + t * 16 * TSTRIDE * 4 + kk * 4);
#pragma unroll
            for (int j = 0; j < 2; j++)
                ldsm4(bf[2*j][0], bf[2*j][1], bf[2*j+1][0], bf[2*j+1][1],
                      bAddr0 + off + j * 16 * TSTRIDE * 4 + kk * 4);
#pragma unroll
            for (int t = 0; t < 4; t++)
#pragma unroll
                for (int u = 0; u < 4; u++)
                    mma_tf32(acc[t][u], af[t], bf[u]);
        }
        __syncthreads();
    }

#pragma unroll
    for (int t = 0; t < 4; t++) {
        int row_a = row0 + wm + t * 16 + r;
#pragma unroll
        for (int u = 0; u < 4; u++) {
            int col = col0 + wn + u * 8 + cq * 2;
            float b0 = bias[col], b1 = bias[col + 1];
            float2 v0 = {acc[t][u][0] + b0, acc[t][u][1] + b1};
            float2 v1 = {acc[t][u][2] + b0, acc[t][u][3] + b1};
            if (rnd) {
                v0.x = rndtf(v0.x); v0.y = rndtf(v0.y);
                v1.x = rndtf(v1.x); v1.y = rndtf(v1.y);
            }
            *(float2*)(C + (size_t)row_a * N + col) = v0;
            *(float2*)(C + (size_t)(row_a + 8) * N + col) = v1;
        }
    }
}

// ---------------------------------------------------------------------------
// g1 split-K partial (tf32 LDSM, 4-stage): BM=32, N=RR=128, K chunk 512.
// partial[row,:] = x[row,:] @ Wg1t[l,g]^T over k in [split*512, +512)
// ---------------------------------------------------------------------------
__global__ __launch_bounds__(256)
void tgemm_g1p(int l)
{
    const int g = blockIdx.z;
    const int cnt = g_cnt[g];
    const int mbase = blockIdx.y * 32;
    if (mbase >= cnt) return;
    const int split = blockIdx.x;
    const int kstart = split * (HH / 4);
    const int* rows = g_rows + g * BB;
    const float* Bt = g_Wg1t + ((size_t)(l * GG + g)) * HH * RR;  // [RR][HH]
    float* outp = g_h1p[split];

    extern __shared__ float sm[];
    int* rows_s = (int*)(sm + 4 * G1_STG);
    const uint32_t sbase = (uint32_t)__cvta_generic_to_shared(sm);

    const int tid = threadIdx.x, lane = tid & 31, wid = tid >> 5;
    const int wn = wid * 16;
    const int r = lane >> 2, cq = lane & 3;

    if (tid < 32) {
        int lr = mbase + tid;
        rows_s[tid] = rows[lr < cnt ? lr : (cnt - 1)];
    }
    __syncthreads();

    const uint32_t aAddr0 = sbase +
        (((lane & 15)) * TSTRIDE + ((lane >> 4) << 2)) * 4;
    const uint32_t bAddr0 = sbase + G1_A * 4 +
        ((wn + ((lane >> 4) << 3) + (lane & 7)) * TSTRIDE +
         (((lane >> 3) & 1) << 2)) * 4;

    float acc[2][2][4];
#pragma unroll
    for (int t = 0; t < 2; t++)
#pragma unroll
        for (int u = 0; u < 2; u++)
#pragma unroll
            for (int v = 0; v < 4; v++) acc[t][u][v] = 0.0f;

    const int NT = 16;  // 512 / 32
    auto load_tile = [&](int st, int k0) {
        const uint32_t sA = sbase + st * G1_STG * 4;
        const uint32_t sB = sA + G1_A * 4;
        {   // A: 32 rows x 8 chunks = 256
            int m = tid >> 3, kc = (tid & 7) * 4;
            cp16(sA + (m * TSTRIDE + kc) * 4,
                 g_x + (size_t)rows_s[m] * HH + k0 + kc);
        }
#pragma unroll
        for (int i = 0; i < 4; i++) {
            int cc = tid + i * 256;
            int m = cc >> 3, kc = (cc & 7) * 4;
            cp16(sB + (m * TSTRIDE + kc) * 4,
                 Bt + (size_t)m * HH + k0 + kc);
        }
    };

#pragma unroll
    for (int p = 0; p < 3; p++) { load_tile(p, kstart + p * 32); CP_COMMIT(); }

    for (int kt = 0; kt < NT; kt++) {
        if (kt + 3 < NT) load_tile((kt + 3) & 3, kstart + (kt + 3) * 32);
        CP_COMMIT();
        CP_WAITG(3);
        __syncthreads();
        const uint32_t off = (kt & 3) * G1_STG * 4;
#pragma unroll
        for (int kk = 0; kk < 32; kk += 8) {
            uint32_t af[2][4], bf[2][2];
#pragma unroll
            for (int t = 0; t < 2; t++)
                ldsm4(af[t][0], af[t][1], af[t][2], af[t][3],
                      aAddr0 + off + t * 16 * TSTRIDE * 4 + kk * 4);
            ldsm4(bf[0][0], bf[0][1], bf[1][0], bf[1][1],
                  bAddr0 + off + kk * 4);
#pragma unroll
            for (int t = 0; t < 2; t++)
#pragma unroll
                for (int u = 0; u < 2; u++)
                    mma_tf32(acc[t][u], af[t], bf[u]);
        }
        __syncthreads();
    }

#pragma unroll
    for (int t = 0; t < 2; t++) {
        int lr0 = mbase + t * 16 + r;
#pragma unroll
        for (int u = 0; u < 2; u++) {
            int col = wn + u * 8 + cq * 2;
            if (lr0 < cnt) {
                int row = rows[lr0];
                float2 v = {acc[t][u][0], acc[t][u][1]};
                *(float2*)(outp + (size_t)row * RR + col) = v;
            }
            if (lr0 + 8 < cnt) {
                int row = rows[lr0 + 8];
                float2 v = {acc[t][u][2], acc[t][u][3]};
                *(float2*)(outp + (size_t)row * RR + col) = v;
            }
        }
    }
}

// h1 = rndtf(sum of 4 partials + b_g1[l, eid])
__global__ void reduce_h1(int l)
{
    int idx = blockIdx.x * 256 + threadIdx.x;   // BB*RR / 256 blocks
    int b = idx >> 7, c = idx & 127;
    float v = g_h1p[0][idx] + g_h1p[1][idx] + g_h1p[2][idx] + g_h1p[3][idx];
    v += g_bg1_ptr[(l * GG + g_eid[b]) * RR + c];
    g_h1[idx] = rndtf(v);
}

// ---------------------------------------------------------------------------
// g2 + fused ELU (tf32 LDSM): BM=128, BN=128, K=RR=128.
// x_next = rndtf(elu(y + h1 @ Wg2t[l,g]^T + b_g2[l,g]))
// ---------------------------------------------------------------------------
__global__ __launch_bounds__(256)
void tgemm_g2(const float* __restrict__ bg2, int l)
{
    const int g = blockIdx.z;
    const int cnt = g_cnt[g];
    const int mbase = blockIdx.y * 128;
    if (mbase >= cnt) return;
    const int* rows = g_rows + g * BB;
    const int col0 = blockIdx.x * 128;
    const float* Bt   = g_Wg2t + ((size_t)(l * GG + g)) * RR * HH;  // [HH][RR]
    const float* bias = bg2 + (size_t)(l * GG + g) * HH;

    extern __shared__ float sm[];
    int* rows_s = (int*)(sm + 2 * STG);
    const uint32_t sbase = (uint32_t)__cvta_generic_to_shared(sm);

    const int tid = threadIdx.x, lane = tid & 31, wid = tid >> 5;
    const int wm = (wid & 1) * 64, wn = (wid >> 1) * 32;
    const int r = lane >> 2, cq = lane & 3;

    if (tid < 128) {
        int lr = mbase + tid;
        rows_s[tid] = rows[lr < cnt ? lr : (cnt - 1)];
    }
    __syncthreads();

    const uint32_t aAddr0 = sbase +
        ((wm + (lane & 15)) * TSTRIDE + ((lane >> 4) << 2)) * 4;
    const uint32_t bAddr0 = sbase + STG_A * 4 +
        ((wn + ((lane >> 4) << 3) + (lane & 7)) * TSTRIDE +
         (((lane >> 3) & 1) << 2)) * 4;

    float acc[4][4][4];
#pragma unroll
    for (int t = 0; t < 4; t++)
#pragma unroll
        for (int u = 0; u < 4; u++)
#pragma unroll
            for (int v = 0; v < 4; v++) acc[t][u][v] = 0.0f;

    const int NT = RR >> 5;  // 4
    auto load_tile = [&](int st, int k0) {
        const uint32_t sA = sbase + st * STG * 4;
        const uint32_t sB = sA + STG_A * 4;
#pragma unroll
        for (int i = 0; i < 4; i++) {
            int cc = tid + i * 256;
            int m = cc >> 3, kc = (cc & 7) * 4;
            cp16(sA + (m * TSTRIDE + kc) * 4,
                 g_h1 + (size_t)rows_s[m] * RR + k0 + kc);
            cp16(sB + (m * TSTRIDE + kc) * 4,
                 Bt + (size_t)(col0 + m) * RR + k0 + kc);
        }
    };

    load_tile(0, 0);
    CP_COMMIT();
    for (int kt = 0; kt < NT; kt++) {
        if (kt + 1 < NT) load_tile((kt + 1) & 1, (kt + 1) << 5);
        CP_COMMIT();
        CP_WAITG(1);
        __syncthreads();
        const uint32_t off = (kt & 1) * STG * 4;
#pragma unroll
        for (int kk = 0; kk < 32; kk += 8) {
            uint32_t af[4][4], bf[4][2];
#pragma unroll
            for (int t = 0; t < 4; t++)
                ldsm4(af[t][0], af[t][1], af[t][2], af[t][3],
                      aAddr0 + off + t * 16 * TSTRIDE * 4 + kk * 4);
#pragma unroll
            for (int j = 0; j < 2; j++)
                ldsm4(bf[2*j][0], bf[2*j][1], bf[2*j+1][0], bf[2*j+1][1],
                      bAddr0 + off + j * 16 * TSTRIDE * 4 + kk * 4);
#pragma unroll
            for (int t = 0; t < 4; t++)
#pragma unroll
                for (int u = 0; u < 4; u++)
                    mma_tf32(acc[t][u], af[t], bf[u]);
        }
        __syncthreads();
    }

#pragma unroll
    for (int t = 0; t < 4; t++) {
        int lr0 = mbase + wm + t * 16 + r;
#pragma unroll
        for (int u = 0; u < 4; u++) {
            int col = col0 + wn + u * 8 + cq * 2;
            float b0 = bias[col], b1 = bias[col + 1];
            if (lr0 < cnt) {
                int row = rows[lr0];
                const float* yp = g_y + (size_t)row * HH + col;
                float2 v = {rndtf(elu1(yp[0] + acc[t][u][0] + b0)),
                            rndtf(elu1(yp[1] + acc[t][u][1] + b1))};
                *(float2*)(g_x + (size_t)row * HH + col) = v;
            }
            if (lr0 + 8 < cnt) {
                int row = rows[lr0 + 8];
                const float* yp = g_y + (size_t)row * HH + col;
                float2 v = {rndtf(elu1(yp[0] + acc[t][u][2] + b0)),
                            rndtf(elu1(yp[1] + acc[t][u][3] + b1))};
                *(float2*)(g_x + (size_t)row * HH + col) = v;
            }
        }
    }
}

// ---------------------------------------------------------------------------
// Output GEMM split-K partials (fp32 SIMT): chunk 256 of K per split.
// ---------------------------------------------------------------------------
__global__ __launch_bounds__(256, 2)
void sgemm_out_part(const float* __restrict__ A, const float* __restrict__ W)
{
    __shared__ __align__(16) float As2[8][128];
    __shared__ __align__(16) float Bs2[8][64];
    const int tid = threadIdx.x;
    const int tx = tid & 15, ty = tid >> 4;
    const int row0 = blockIdx.y * 128;
    const int split = blockIdx.z;
    float* outp = g_outp[split];

    const int a_row = tid >> 1;
    const int a_col = (tid & 1) * 4;

    float acc[8][4];
#pragma unroll
    for (int i = 0; i < 8; i++)
#pragma unroll
        for (int j = 0; j < 4; j++) acc[i][j] = 0.0f;

    const int kbeg = split * 256, kend = kbeg + 256;
    for (int k0 = kbeg; k0 < kend; k0 += 8) {
        float4 av = *(const float4*)(A + (size_t)(row0 + a_row) * HH + k0 + a_col);
        As2[a_col + 0][a_row] = av.x;
        As2[a_col + 1][a_row] = av.y;
        As2[a_col + 2][a_row] = av.z;
        As2[a_col + 3][a_row] = av.w;
        if (tid < 128) {
            int br = tid >> 4, bc = (tid & 15) * 4;
            *(float4*)(&Bs2[br][bc]) =
                *(const float4*)(W + (size_t)(k0 + br) * AA + bc);
        }
        __syncthreads();
#pragma unroll
        for (int k = 0; k < 8; k++) {
            float4 a0 = *(const float4*)(&As2[k][ty * 8]);
            float4 a1 = *(const float4*)(&As2[k][ty * 8 + 4]);
            float4 b0 = *(const float4*)(&Bs2[k][tx * 4]);
            float ar[8] = {a0.x, a0.y, a0.z, a0.w, a1.x, a1.y, a1.z, a1.w};
            float br4[4] = {b0.x, b0.y, b0.z, b0.w};
#pragma unroll
            for (int i = 0; i < 8; i++)
#pragma unroll
                for (int j = 0; j < 4; j++)
                    acc[i][j] = fmaf(ar[i], br4[j], acc[i][j]);
        }
        __syncthreads();
    }

    const int c = tx * 4;
#pragma unroll
    for (int i = 0; i < 8; i++) {
        int r = row0 + ty * 8 + i;
        float4 v = {acc[i][0], acc[i][1], acc[i][2], acc[i][3]};
        *(float4*)(outp + (size_t)r * AA + c) = v;
    }
}

__global__ void reduce_out(const float* __restrict__ bout,
                           float* __restrict__ out)
{
    int idx = blockIdx.x * 256 + threadIdx.x;  // BB*AA / 256 blocks
    float v = 0.0f;
#pragma unroll
    for (int p = 0; p < 8; p++) v += g_outp[p][idx];
    out[idx] = v + bout[idx & (AA - 1)];
}

// ---------------------------------------------------------------------------
// Launch
// ---------------------------------------------------------------------------
extern "C" void kernel_launch(void* const* d_in, const int* in_sizes, int n_in,
                              void* d_out, int out_size)
{
    const float* s = 0; const float* W_in = 0; const float* b_in = 0;
    const float* W_main = 0; const float* b_main = 0; const float* b_g2 = 0;
    const float* W_out = 0; const float* b_out = 0;
    const float* w8[2] = {0, 0};
    const void*  c4[2] = {0, 0};
    int n8 = 0, n4 = 0;

    for (int i = 0; i < n_in; i++) {
        switch (in_sizes[i]) {
            case 2097152:  s      = (const float*)d_in[i]; break;
            case 1048576:  W_in   = (const float*)d_in[i]; break;
            case 2048:     b_in   = (const float*)d_in[i]; break;
            case 16777216: W_main = (const float*)d_in[i]; break;
            case 8192:     b_main = (const float*)d_in[i]; break;
            case 65536:    b_g2   = (const float*)d_in[i]; break;
            case 131072:   W_out  = (const float*)d_in[i]; break;
            case 64:       b_out  = (const float*)d_in[i]; break;
            case 8388608:  if (n8 < 2) w8[n8++] = (const float*)d_in[i]; break;
            case 4096:     if (n4 < 2) c4[n4++] = d_in[i]; break;
            default: break;
        }
    }
    const float* W_g1 = w8[0];
    const float* W_g2 = w8[1];
    float* out = (float*)d_out;

    float* x_ptr;    cudaGetSymbolAddress((void**)&x_ptr, g_x);
    float* y_ptr;    cudaGetSymbolAddress((void**)&y_ptr, g_y);
    float* sr_ptr;   cudaGetSymbolAddress((void**)&sr_ptr, g_sr);
    float* wmt_ptr;  cudaGetSymbolAddress((void**)&wmt_ptr, g_Wmt);
    float* wg1t_ptr; cudaGetSymbolAddress((void**)&wg1t_ptr, g_Wg1t);
    float* wg2t_ptr; cudaGetSymbolAddress((void**)&wg2t_ptr, g_Wg2t);
    float* wint_ptr; cudaGetSymbolAddress((void**)&wint_ptr, g_Wint);

    const int smem_big = 2 * STG * 4;                 // 73728
    const int smem_g2  = 2 * STG * 4 + 128 * 4;       // 74240
    const int smem_g1  = 4 * G1_STG * 4 + 32 * 4;     // 92288
    cudaFuncSetAttribute(tgemm_t,  cudaFuncAttributeMaxDynamicSharedMemorySize, smem_big);
    cudaFuncSetAttribute(tgemm_g2, cudaFuncAttributeMaxDynamicSharedMemorySize, smem_g2);
    cudaFuncSetAttribute(tgemm_g1p,cudaFuncAttributeMaxDynamicSharedMemorySize, smem_g1);

    dim3 blk(256);
    dim3 tblk(32, 8);

    build_routing<<<1, 256>>>((const int*)c4[0], (const int*)c4[1]);

    // prep: tf32 rounding (+ transpose for weights)
    round_s<<<BB * SS / 1024, 256>>>(s);
    transpose_rna<<<dim3(HH / 32, SS / 32, 1), tblk>>>(W_in, wint_ptr, SS, HH);
    transpose_rna<<<dim3(HH / 32, HH / 32, LL), tblk>>>(W_main, wmt_ptr, HH, HH);
    transpose_rna<<<dim3(RR / 32, HH / 32, LL * GG), tblk>>>(W_g1, wg1t_ptr, HH, RR);
    transpose_rna<<<dim3(HH / 32, RR / 32, LL * GG), tblk>>>(W_g2, wg2t_ptr, RR, HH);

    // x = rndtf(s @ W_in + b_in)
    tgemm_t<<<dim3(HH / 128, BB / 128), blk, smem_big>>>(
        sr_ptr, SS, wint_ptr, SS, b_in, x_ptr, HH, SS, 1);

    for (int l = 0; l < LL; l++) {
        // y = x @ W_main[l] + b_main[l]   (fp32, not rounded)
        tgemm_t<<<dim3(HH / 128, BB / 128), blk, smem_big>>>(
            x_ptr, HH, wmt_ptr + (size_t)l * HH * HH, HH,
            b_main + (size_t)l * HH, y_ptr, HH, HH, 0);
        // h1 partials + reduce
        tgemm_g1p<<<dim3(4, BB / 32, GG), blk, smem_g1>>>(l);
        reduce_h1<<<BB * RR / 256, 256>>>(l);
        // x = rndtf(elu(y + h1 @ W_g2[l,o] + b_g2))
        tgemm_g2<<<dim3(HH / 128, BB / 128, GG), blk, smem_g2>>>(b_g2, l);
    }

    // out = x @ W_out + b_out  (split-K 8 + reduce)
    sgemm_out_part<<<dim3(1, BB / 128, 8), blk>>>(x_ptr, W_out);
    reduce_out<<<BB * AA / 256, 256>>>(b_out, out);
}

// round 9
// speedup vs baseline: 6.0704x; 1.4791x over previous
#include <cuda_runtime.h>
#include <cuda_fp16.h>
#include <math.h>
#include <stdint.h>

// Problem constants  (L,G,H,R,S,A,B = 4,8,2048,128,512,64,4096)
#define BB 4096
#define SS 512
#define HH 2048
#define RR 128
#define AA 64
#define GG 8
#define LL 4

// ---------------------------------------------------------------------------
// Scratch (device globals)
// ---------------------------------------------------------------------------
__device__ __align__(16) __half g_x[(size_t)BB * HH];     // activations (fp16)
__device__ __align__(16) float  g_y[(size_t)BB * HH];     // main branch (fp32)
__device__ __align__(16) __half g_h1[(size_t)BB * RR];    // low-rank mid (fp16)
__device__ __align__(16) float  g_h1p[4][(size_t)BB * RR];
__device__ __align__(16) float  g_outp[8][(size_t)BB * AA];
__device__ __align__(16) __half g_Wmt[(size_t)LL * HH * HH];       // W_main^T
__device__ __align__(16) __half g_Wg1t[(size_t)LL * GG * HH * RR]; // W_g1^T
__device__ __align__(16) __half g_Wg2t[(size_t)LL * GG * RR * HH]; // W_g2^T
__device__ __align__(16) __half g_Wint[(size_t)SS * HH];           // W_in^T
__device__ __align__(16) __half g_sr[(size_t)BB * SS];             // s fp16
__device__ int g_cnt[GG];
__device__ int g_rows[GG * BB];
__device__ int g_eid[BB];
__device__ const float* g_bg1_ptr;

// ---------------------------------------------------------------------------
// helpers
// ---------------------------------------------------------------------------
__device__ __forceinline__ void mma_f16(float* d, const uint32_t* a,
                                        const uint32_t* b) {
    asm volatile(
        "mma.sync.aligned.m16n8k16.row.col.f32.f16.f16.f32 "
        "{%0,%1,%2,%3}, {%4,%5,%6,%7}, {%8,%9}, {%0,%1,%2,%3};"
        : "+f"(d[0]), "+f"(d[1]), "+f"(d[2]), "+f"(d[3])
        : "r"(a[0]), "r"(a[1]), "r"(a[2]), "r"(a[3]), "r"(b[0]), "r"(b[1]));
}
__device__ __forceinline__ void ldsm4(uint32_t& r0, uint32_t& r1, uint32_t& r2,
                                      uint32_t& r3, uint32_t addr) {
    asm volatile("ldmatrix.sync.aligned.m8n8.x4.shared.b16 {%0,%1,%2,%3}, [%4];"
                 : "=r"(r0), "=r"(r1), "=r"(r2), "=r"(r3) : "r"(addr));
}
__device__ __forceinline__ float elu1(float v) {
    return v > 0.0f ? v : expm1f(v);
}
__device__ __forceinline__ void cp16(uint32_t s, const void* g) {
    asm volatile("cp.async.ca.shared.global [%0], [%1], 16;" :: "r"(s), "l"(g));
}
#define CP_COMMIT() asm volatile("cp.async.commit_group;")
#define CP_WAITG(n) asm volatile("cp.async.wait_group %0;" :: "n"(n))

#define HSTR 40                  // halves per smem row (32 data + 8 pad = 80B)
#define H_TILE (128 * HSTR)      // halves per 128-row tile
#define H_STG  (2 * H_TILE)      // halves per stage (A+B), 20480 B
#define G1_A_H (32 * HSTR)       // halves per 32-row A tile
#define G1_STG_H (G1_A_H + H_TILE)  // 6400 halves = 12800 B

// ---------------------------------------------------------------------------
// Routing (resolves {o, b_g1} size-4096 ambiguity by content)
// ---------------------------------------------------------------------------
__global__ void build_routing(const int* __restrict__ c0,
                              const int* __restrict__ c1)
{
    __shared__ const int* o_ptr;
    __shared__ int stride;
    int tid = threadIdx.x;
    if (tid == 0) {
        const int* cands[2] = {c0, c1};
        int pick = 0; stride = 1;
        for (int c = 0; c < 2; c++) {
            const int* p = cands[c];
            bool ok32 = true, nz32 = false;
            for (int i = 0; i < 256; i++) {
                int v = p[i];
                if (v < 0 || v >= GG) { ok32 = false; break; }
                if (v) nz32 = true;
            }
            if (ok32 && nz32) { pick = c; stride = 1; break; }
            bool ok64 = true, nz64 = false;
            for (int i = 0; i < 256; i++) {
                int lo = p[2 * i], hi = p[2 * i + 1];
                if (hi != 0 || lo < 0 || lo >= GG) { ok64 = false; break; }
                if (lo) nz64 = true;
            }
            if (ok64 && nz64) { pick = c; stride = 2; break; }
        }
        o_ptr = cands[pick];
        g_bg1_ptr = (const float*)cands[1 - pick];
    }
    if (tid < GG) g_cnt[tid] = 0;
    __syncthreads();
    const int* o = o_ptr;
    const int st = stride;
    for (int b = tid; b < BB; b += blockDim.x) {
        int e = o[(size_t)b * st];
        g_eid[b] = e;
        int idx = atomicAdd(&g_cnt[e], 1);
        g_rows[e * BB + idx] = b;
    }
}

// ---------------------------------------------------------------------------
// Prep: transpose + fp16 convert. src [K][N] fp32 (batched) -> dst [N][K] fp16.
// ---------------------------------------------------------------------------
__global__ void transpose_h(const float* __restrict__ src,
                            __half* __restrict__ dst, int K, int N)
{
    __shared__ float t[32][33];
    const size_t mb = (size_t)blockIdx.z * K * N;
    int k0 = blockIdx.y * 32, n0 = blockIdx.x * 32;
    int x = threadIdx.x, y = threadIdx.y;  // 32x8
#pragma unroll
    for (int i = y; i < 32; i += 8)
        t[i][x] = src[mb + (size_t)(k0 + i) * N + n0 + x];
    __syncthreads();
#pragma unroll
    for (int i = y; i < 32; i += 8)
        dst[mb + (size_t)(n0 + i) * K + k0 + x] = __float2half(t[x][i]);
}

__global__ void round_s(const float* __restrict__ s)
{
    int idx = (blockIdx.x * 256 + threadIdx.x) * 4;
    float4 v = *(const float4*)(s + idx);
    *(__half2*)(g_sr + idx)     = __floats2half2_rn(v.x, v.y);
    *(__half2*)(g_sr + idx + 2) = __floats2half2_rn(v.z, v.w);
}

// ---------------------------------------------------------------------------
// Dense fp16 GEMM (m16n8k16), 3-stage cp.async ring.
// C[M,N] = A[M,K] @ Bt[N,K]^T + bias.  BM=BN=128, BK=32, 256 thr (8 warps
// 64x32 each).  Cf!=0 -> fp32 out; else Ch (fp16 out).
// ---------------------------------------------------------------------------
__global__ __launch_bounds__(256)
void hgemm(const __half* __restrict__ A, int lda,
           const __half* __restrict__ Bt, int ldb,
           const float* __restrict__ bias, float* Cf, __half* Ch,
           int N, int K)
{
    extern __shared__ __half hsm[];
    const int tid = threadIdx.x, lane = tid & 31, wid = tid >> 5;
    const int wm = (wid & 1) * 64, wn = (wid >> 1) * 32;
    const int row0 = blockIdx.y * 128, col0 = blockIdx.x * 128;
    const int r = lane >> 2, cq = lane & 3;
    const uint32_t sbase = (uint32_t)__cvta_generic_to_shared(hsm);

    const uint32_t aAddr0 = sbase +
        ((wm + (lane & 15)) * HSTR + ((lane >> 4) << 3)) * 2;
    const uint32_t bAddr0 = sbase + H_TILE * 2 +
        ((wn + ((lane >> 4) << 3) + (lane & 7)) * HSTR +
         (((lane >> 3) & 1) << 3)) * 2;

    float acc[4][4][4];
#pragma unroll
    for (int t = 0; t < 4; t++)
#pragma unroll
        for (int u = 0; u < 4; u++)
#pragma unroll
            for (int v = 0; v < 4; v++) acc[t][u][v] = 0.0f;

    const int NT = K >> 5;
    auto load_tile = [&](int slot, int k0) {
        const uint32_t sA = sbase + slot * H_STG * 2;
        const uint32_t sB = sA + H_TILE * 2;
#pragma unroll
        for (int i = 0; i < 2; i++) {
            int cc = tid + i * 256;
            int m = cc >> 2, c = cc & 3;
            cp16(sA + (m * HSTR + c * 8) * 2,
                 A + (size_t)(row0 + m) * lda + k0 + c * 8);
            cp16(sB + (m * HSTR + c * 8) * 2,
                 Bt + (size_t)(col0 + m) * ldb + k0 + c * 8);
        }
    };

    load_tile(0, 0);  CP_COMMIT();
    load_tile(1, 32); CP_COMMIT();

    for (int kt = 0; kt < NT; kt++) {
        if (kt + 2 < NT) load_tile((kt + 2) % 3, (kt + 2) * 32);
        CP_COMMIT();
        CP_WAITG(2);
        __syncthreads();
        const uint32_t off = (kt % 3) * H_STG * 2;
#pragma unroll
        for (int ks = 0; ks < 2; ks++) {
            const uint32_t kb = ks * 32;   // 16 halves = 32 bytes
            uint32_t af[4][4], bf[4][2];
#pragma unroll
            for (int t = 0; t < 4; t++)
                ldsm4(af[t][0], af[t][1], af[t][2], af[t][3],
                      aAddr0 + off + t * 16 * HSTR * 2 + kb);
#pragma unroll
            for (int j = 0; j < 2; j++)
                ldsm4(bf[2*j][0], bf[2*j][1], bf[2*j+1][0], bf[2*j+1][1],
                      bAddr0 + off + j * 16 * HSTR * 2 + kb);
#pragma unroll
            for (int t = 0; t < 4; t++)
#pragma unroll
                for (int u = 0; u < 4; u++)
                    mma_f16(acc[t][u], af[t], bf[u]);
        }
        __syncthreads();
    }

#pragma unroll
    for (int t = 0; t < 4; t++) {
        int row_a = row0 + wm + t * 16 + r;
#pragma unroll
        for (int u = 0; u < 4; u++) {
            int col = col0 + wn + u * 8 + cq * 2;
            float b0 = bias[col], b1 = bias[col + 1];
            float v00 = acc[t][u][0] + b0, v01 = acc[t][u][1] + b1;
            float v10 = acc[t][u][2] + b0, v11 = acc[t][u][3] + b1;
            if (Cf) {
                *(float2*)(Cf + (size_t)row_a * N + col) = {v00, v01};
                *(float2*)(Cf + (size_t)(row_a + 8) * N + col) = {v10, v11};
            } else {
                *(__half2*)(Ch + (size_t)row_a * N + col) =
                    __floats2half2_rn(v00, v01);
                *(__half2*)(Ch + (size_t)(row_a + 8) * N + col) =
                    __floats2half2_rn(v10, v11);
            }
        }
    }
}

// ---------------------------------------------------------------------------
// g1 split-K partial (fp16, 4-stage): BM=32, N=RR=128, K chunk 512.
// ---------------------------------------------------------------------------
__global__ __launch_bounds__(256)
void hgemm_g1p(int l)
{
    const int g = blockIdx.z;
    const int cnt = g_cnt[g];
    const int mbase = blockIdx.y * 32;
    if (mbase >= cnt) return;
    const int split = blockIdx.x;
    const int kstart = split * (HH / 4);
    const int* rows = g_rows + g * BB;
    const __half* Bt = g_Wg1t + ((size_t)(l * GG + g)) * HH * RR;  // [RR][HH]
    float* outp = g_h1p[split];

    extern __shared__ __half hsm[];
    int* rows_s = (int*)(hsm + 4 * G1_STG_H);
    const uint32_t sbase = (uint32_t)__cvta_generic_to_shared(hsm);

    const int tid = threadIdx.x, lane = tid & 31, wid = tid >> 5;
    const int wn = wid * 16;
    const int r = lane >> 2, cq = lane & 3;

    if (tid < 32) {
        int lr = mbase + tid;
        rows_s[tid] = rows[lr < cnt ? lr : (cnt - 1)];
    }
    __syncthreads();

    const uint32_t aAddr0 = sbase +
        ((lane & 15) * HSTR + ((lane >> 4) << 3)) * 2;
    const uint32_t bAddr0 = sbase + G1_A_H * 2 +
        ((wn + ((lane >> 4) << 3) + (lane & 7)) * HSTR +
         (((lane >> 3) & 1) << 3)) * 2;

    float acc[2][2][4];
#pragma unroll
    for (int t = 0; t < 2; t++)
#pragma unroll
        for (int u = 0; u < 2; u++)
#pragma unroll
            for (int v = 0; v < 4; v++) acc[t][u][v] = 0.0f;

    const int NT = 16;   // 512/32
    auto load_tile = [&](int slot, int k0) {
        const uint32_t sA = sbase + slot * G1_STG_H * 2;
        const uint32_t sB = sA + G1_A_H * 2;
        if (tid < 128) {   // A: 32 rows x 4 chunks
            int m = tid >> 2, c = tid & 3;
            cp16(sA + (m * HSTR + c * 8) * 2,
                 g_x + (size_t)rows_s[m] * HH + k0 + c * 8);
        }
#pragma unroll
        for (int i = 0; i < 2; i++) {  // B: 128 rows x 4 chunks
            int cc = tid + i * 256;
            int m = cc >> 2, c = cc & 3;
            cp16(sB + (m * HSTR + c * 8) * 2,
                 Bt + (size_t)m * HH + k0 + c * 8);
        }
    };

#pragma unroll
    for (int p = 0; p < 3; p++) { load_tile(p, kstart + p * 32); CP_COMMIT(); }

    for (int kt = 0; kt < NT; kt++) {
        if (kt + 3 < NT) load_tile((kt + 3) & 3, kstart + (kt + 3) * 32);
        CP_COMMIT();
        CP_WAITG(3);
        __syncthreads();
        const uint32_t off = (kt & 3) * G1_STG_H * 2;
#pragma unroll
        for (int ks = 0; ks < 2; ks++) {
            const uint32_t kb = ks * 32;
            uint32_t af[2][4], bf[2][2];
#pragma unroll
            for (int t = 0; t < 2; t++)
                ldsm4(af[t][0], af[t][1], af[t][2], af[t][3],
                      aAddr0 + off + t * 16 * HSTR * 2 + kb);
            ldsm4(bf[0][0], bf[0][1], bf[1][0], bf[1][1], bAddr0 + off + kb);
#pragma unroll
            for (int t = 0; t < 2; t++)
#pragma unroll
                for (int u = 0; u < 2; u++)
                    mma_f16(acc[t][u], af[t], bf[u]);
        }
        __syncthreads();
    }

#pragma unroll
    for (int t = 0; t < 2; t++) {
        int lr0 = mbase + t * 16 + r;
#pragma unroll
        for (int u = 0; u < 2; u++) {
            int col = wn + u * 8 + cq * 2;
            if (lr0 < cnt) {
                int row = rows[lr0];
                *(float2*)(outp + (size_t)row * RR + col) =
                    {acc[t][u][0], acc[t][u][1]};
            }
            if (lr0 + 8 < cnt) {
                int row = rows[lr0 + 8];
                *(float2*)(outp + (size_t)row * RR + col) =
                    {acc[t][u][2], acc[t][u][3]};
            }
        }
    }
}

// h1 = fp16(sum of 4 partials + b_g1[l, eid])
__global__ void reduce_h1(int l)
{
    int idx = blockIdx.x * 256 + threadIdx.x;
    int b = idx >> 7, c = idx & 127;
    float v = g_h1p[0][idx] + g_h1p[1][idx] + g_h1p[2][idx] + g_h1p[3][idx];
    v += g_bg1_ptr[(l * GG + g_eid[b]) * RR + c];
    g_h1[idx] = __float2half(v);
}

// ---------------------------------------------------------------------------
// g2 + fused ELU (fp16): BM=128, BN=128, K=RR=128, 3-stage.
// x_next = fp16(elu(y + h1 @ Wg2t[l,g]^T + b_g2[l,g]))
// ---------------------------------------------------------------------------
__global__ __launch_bounds__(256)
void hgemm_g2(const float* __restrict__ bg2, int l)
{
    const int g = blockIdx.z;
    const int cnt = g_cnt[g];
    const int mbase = blockIdx.y * 128;
    if (mbase >= cnt) return;
    const int* rows = g_rows + g * BB;
    const int col0 = blockIdx.x * 128;
    const __half* Bt  = g_Wg2t + ((size_t)(l * GG + g)) * RR * HH;  // [HH][RR]
    const float* bias = bg2 + (size_t)(l * GG + g) * HH;

    extern __shared__ __half hsm[];
    int* rows_s = (int*)(hsm + 3 * H_STG);
    const uint32_t sbase = (uint32_t)__cvta_generic_to_shared(hsm);

    const int tid = threadIdx.x, lane = tid & 31, wid = tid >> 5;
    const int wm = (wid & 1) * 64, wn = (wid >> 1) * 32;
    const int r = lane >> 2, cq = lane & 3;

    if (tid < 128) {
        int lr = mbase + tid;
        rows_s[tid] = rows[lr < cnt ? lr : (cnt - 1)];
    }
    __syncthreads();

    const uint32_t aAddr0 = sbase +
        ((wm + (lane & 15)) * HSTR + ((lane >> 4) << 3)) * 2;
    const uint32_t bAddr0 = sbase + H_TILE * 2 +
        ((wn + ((lane >> 4) << 3) + (lane & 7)) * HSTR +
         (((lane >> 3) & 1) << 3)) * 2;

    float acc[4][4][4];
#pragma unroll
    for (int t = 0; t < 4; t++)
#pragma unroll
        for (int u = 0; u < 4; u++)
#pragma unroll
            for (int v = 0; v < 4; v++) acc[t][u][v] = 0.0f;

    const int NT = RR >> 5;  // 4
    auto load_tile = [&](int slot, int k0) {
        const uint32_t sA = sbase + slot * H_STG * 2;
        const uint32_t sB = sA + H_TILE * 2;
#pragma unroll
        for (int i = 0; i < 2; i++) {
            int cc = tid + i * 256;
            int m = cc >> 2, c = cc & 3;
            cp16(sA + (m * HSTR + c * 8) * 2,
                 g_h1 + (size_t)rows_s[m] * RR + k0 + c * 8);
            cp16(sB + (m * HSTR + c * 8) * 2,
                 Bt + (size_t)(col0 + m) * RR + k0 + c * 8);
        }
    };

    load_tile(0, 0);  CP_COMMIT();
    load_tile(1, 32); CP_COMMIT();

    for (int kt = 0; kt < NT; kt++) {
        if (kt + 2 < NT) load_tile((kt + 2) % 3, (kt + 2) * 32);
        CP_COMMIT();
        CP_WAITG(2);
        __syncthreads();
        const uint32_t off = (kt % 3) * H_STG * 2;
#pragma unroll
        for (int ks = 0; ks < 2; ks++) {
            const uint32_t kb = ks * 32;
            uint32_t af[4][4], bf[4][2];
#pragma unroll
            for (int t = 0; t < 4; t++)
                ldsm4(af[t][0], af[t][1], af[t][2], af[t][3],
                      aAddr0 + off + t * 16 * HSTR * 2 + kb);
#pragma unroll
            for (int j = 0; j < 2; j++)
                ldsm4(bf[2*j][0], bf[2*j][1], bf[2*j+1][0], bf[2*j+1][1],
                      bAddr0 + off + j * 16 * HSTR * 2 + kb);
#pragma unroll
            for (int t = 0; t < 4; t++)
#pragma unroll
                for (int u = 0; u < 4; u++)
                    mma_f16(acc[t][u], af[t], bf[u]);
        }
        __syncthreads();
    }

#pragma unroll
    for (int t = 0; t < 4; t++) {
        int lr0 = mbase + wm + t * 16 + r;
#pragma unroll
        for (int u = 0; u < 4; u++) {
            int col = col0 + wn + u * 8 + cq * 2;
            float b0 = bias[col], b1 = bias[col + 1];
            if (lr0 < cnt) {
                int row = rows[lr0];
                const float* yp = g_y + (size_t)row * HH + col;
                *(__half2*)(g_x + (size_t)row * HH + col) =
                    __floats2half2_rn(elu1(yp[0] + acc[t][u][0] + b0),
                                      elu1(yp[1] + acc[t][u][1] + b1));
            }
            if (lr0 + 8 < cnt) {
                int row = rows[lr0 + 8];
                const float* yp = g_y + (size_t)row * HH + col;
                *(__half2*)(g_x + (size_t)row * HH + col) =
                    __floats2half2_rn(elu1(yp[0] + acc[t][u][2] + b0),
                                      elu1(yp[1] + acc[t][u][3] + b1));
            }
        }
    }
}

// ---------------------------------------------------------------------------
// Output GEMM split-K partials (fp32 SIMT, fp16 A) + reduce
// ---------------------------------------------------------------------------
__global__ __launch_bounds__(256, 2)
void sgemm_out_part(const __half* __restrict__ A, const float* __restrict__ W)
{
    __shared__ __align__(16) float As2[8][128];
    __shared__ __align__(16) float Bs2[8][64];
    const int tid = threadIdx.x;
    const int tx = tid & 15, ty = tid >> 4;
    const int row0 = blockIdx.y * 128;
    const int split = blockIdx.z;
    float* outp = g_outp[split];

    const int a_row = tid >> 1;
    const int a_col = (tid & 1) * 4;

    float acc[8][4];
#pragma unroll
    for (int i = 0; i < 8; i++)
#pragma unroll
        for (int j = 0; j < 4; j++) acc[i][j] = 0.0f;

    const int kbeg = split * 256, kend = kbeg + 256;
    for (int k0 = kbeg; k0 < kend; k0 += 8) {
        const __half* ap = A + (size_t)(row0 + a_row) * HH + k0 + a_col;
        __half2 p0 = *(const __half2*)ap;
        __half2 p1 = *(const __half2*)(ap + 2);
        As2[a_col + 0][a_row] = __half2float(p0.x);
        As2[a_col + 1][a_row] = __half2float(p0.y);
        As2[a_col + 2][a_row] = __half2float(p1.x);
        As2[a_col + 3][a_row] = __half2float(p1.y);
        if (tid < 128) {
            int br = tid >> 4, bc = (tid & 15) * 4;
            *(float4*)(&Bs2[br][bc]) =
                *(const float4*)(W + (size_t)(k0 + br) * AA + bc);
        }
        __syncthreads();
#pragma unroll
        for (int k = 0; k < 8; k++) {
            float4 a0 = *(const float4*)(&As2[k][ty * 8]);
            float4 a1 = *(const float4*)(&As2[k][ty * 8 + 4]);
            float4 b0 = *(const float4*)(&Bs2[k][tx * 4]);
            float ar[8] = {a0.x, a0.y, a0.z, a0.w, a1.x, a1.y, a1.z, a1.w};
            float br4[4] = {b0.x, b0.y, b0.z, b0.w};
#pragma unroll
            for (int i = 0; i < 8; i++)
#pragma unroll
                for (int j = 0; j < 4; j++)
                    acc[i][j] = fmaf(ar[i], br4[j], acc[i][j]);
        }
        __syncthreads();
    }

    const int c = tx * 4;
#pragma unroll
    for (int i = 0; i < 8; i++) {
        int r = row0 + ty * 8 + i;
        float4 v = {acc[i][0], acc[i][1], acc[i][2], acc[i][3]};
        *(float4*)(outp + (size_t)r * AA + c) = v;
    }
}

__global__ void reduce_out(const float* __restrict__ bout,
                           float* __restrict__ out)
{
    int idx = blockIdx.x * 256 + threadIdx.x;
    float v = 0.0f;
#pragma unroll
    for (int p = 0; p < 8; p++) v += g_outp[p][idx];
    out[idx] = v + bout[idx & (AA - 1)];
}

// ---------------------------------------------------------------------------
// Launch
// ---------------------------------------------------------------------------
extern "C" void kernel_launch(void* const* d_in, const int* in_sizes, int n_in,
                              void* d_out, int out_size)
{
    const float* s = 0; const float* W_in = 0; const float* b_in = 0;
    const float* W_main = 0; const float* b_main = 0; const float* b_g2 = 0;
    const float* W_out = 0; const float* b_out = 0;
    const float* w8[2] = {0, 0};
    const void*  c4[2] = {0, 0};
    int n8 = 0, n4 = 0;

    for (int i = 0; i < n_in; i++) {
        switch (in_sizes[i]) {
            case 2097152:  s      = (const float*)d_in[i]; break;
            case 1048576:  W_in   = (const float*)d_in[i]; break;
            case 2048:     b_in   = (const float*)d_in[i]; break;
            case 16777216: W_main = (const float*)d_in[i]; break;
            case 8192:     b_main = (const float*)d_in[i]; break;
            case 65536:    b_g2   = (const float*)d_in[i]; break;
            case 131072:   W_out  = (const float*)d_in[i]; break;
            case 64:       b_out  = (const float*)d_in[i]; break;
            case 8388608:  if (n8 < 2) w8[n8++] = (const float*)d_in[i]; break;
            case 4096:     if (n4 < 2) c4[n4++] = d_in[i]; break;
            default: break;
        }
    }
    const float* W_g1 = w8[0];
    const float* W_g2 = w8[1];
    float* out = (float*)d_out;

    __half* x_ptr;   cudaGetSymbolAddress((void**)&x_ptr, g_x);
    float*  y_ptr;   cudaGetSymbolAddress((void**)&y_ptr, g_y);
    __half* sr_ptr;  cudaGetSymbolAddress((void**)&sr_ptr, g_sr);
    __half* wmt_ptr; cudaGetSymbolAddress((void**)&wmt_ptr, g_Wmt);
    __half* wg1t_ptr;cudaGetSymbolAddress((void**)&wg1t_ptr, g_Wg1t);
    __half* wg2t_ptr;cudaGetSymbolAddress((void**)&wg2t_ptr, g_Wg2t);
    __half* wint_ptr;cudaGetSymbolAddress((void**)&wint_ptr, g_Wint);

    const int smem_dense = 3 * H_STG * 2;              // 61440
    const int smem_g2    = 3 * H_STG * 2 + 128 * 4;    // 61952
    const int smem_g1    = 4 * G1_STG_H * 2 + 32 * 4;  // 51328
    cudaFuncSetAttribute(hgemm,    cudaFuncAttributeMaxDynamicSharedMemorySize, smem_dense);
    cudaFuncSetAttribute(hgemm_g2, cudaFuncAttributeMaxDynamicSharedMemorySize, smem_g2);
    cudaFuncSetAttribute(hgemm_g1p,cudaFuncAttributeMaxDynamicSharedMemorySize, smem_g1);

    dim3 blk(256);
    dim3 tblk(32, 8);

    build_routing<<<1, 256>>>((const int*)c4[0], (const int*)c4[1]);

    round_s<<<BB * SS / 1024, 256>>>(s);
    transpose_h<<<dim3(HH / 32, SS / 32, 1), tblk>>>(W_in, wint_ptr, SS, HH);
    transpose_h<<<dim3(HH / 32, HH / 32, LL), tblk>>>(W_main, wmt_ptr, HH, HH);
    transpose_h<<<dim3(RR / 32, HH / 32, LL * GG), tblk>>>(W_g1, wg1t_ptr, HH, RR);
    transpose_h<<<dim3(HH / 32, RR / 32, LL * GG), tblk>>>(W_g2, wg2t_ptr, RR, HH);

    // x = fp16(s @ W_in + b_in)
    hgemm<<<dim3(HH / 128, BB / 128), blk, smem_dense>>>(
        sr_ptr, SS, wint_ptr, SS, b_in, nullptr, x_ptr, HH, SS);

    for (int l = 0; l < LL; l++) {
        // y = x @ W_main[l] + b_main[l]  (fp32 out)
        hgemm<<<dim3(HH / 128, BB / 128), blk, smem_dense>>>(
            x_ptr, HH, wmt_ptr + (size_t)l * HH * HH, HH,
            b_main + (size_t)l * HH, y_ptr, nullptr, HH, HH);
        hgemm_g1p<<<dim3(4, BB / 32, GG), blk, smem_g1>>>(l);
        reduce_h1<<<BB * RR / 256, 256>>>(l);
        hgemm_g2<<<dim3(HH / 128, BB / 128, GG), blk, smem_g2>>>(b_g2, l);
    }

    sgemm_out_part<<<dim3(1, BB / 128, 8), blk>>>(x_ptr, W_out);
    reduce_out<<<BB * AA / 256, 256>>>(b_out, out);
}